// round 8
// baseline (speedup 1.0000x reference)
#include <cuda_runtime.h>
#include <cstdint>

#define B_    32
#define CIN   512
#define CI    256
#define NPIX  3136
#define EPSV  1e-5f

// ---------------- scratch (static device globals; no allocation) ----------------
__device__ float d_TPG[(size_t)B_ * 3 * CI * NPIX];   // [b][768][3136]: theta|phi|g (tf32-rounded)
__device__ float d_F  [(size_t)B_ * CI * CI];         // [b][256][256]  (tf32-rounded)
__device__ float d_Y  [(size_t)B_ * CI * NPIX];       // [b][256][3136] (tf32-rounded)
__device__ float d_Wcat[3 * CI * CIN];                // tf32-rounded
__device__ float d_Wr  [CIN * CI];                    // tf32-rounded W_w
__device__ float d_Bcat[3 * CI];
__device__ float d_Sum[CIN];
__device__ float d_Sq [CIN];
__device__ float d_Scale[CIN];
__device__ float d_Shift[CIN];

// ================= PTX helpers (sm_80+-portable) =================
__device__ __forceinline__ uint32_t smem_u32(const void* p) {
    uint32_t a;
    asm("{ .reg .u64 t; cvta.to.shared.u64 t, %1; cvt.u32.u64 %0, t; }" : "=r"(a) : "l"(p));
    return a;
}
__device__ __forceinline__ void cp16(uint32_t d, const void* s, bool ok) {
    int sz = ok ? 16 : 0;
    asm volatile("cp.async.cg.shared.global [%0], [%1], 16, %2;" :: "r"(d), "l"(s), "r"(sz) : "memory");
}
__device__ __forceinline__ void cp_commit() { asm volatile("cp.async.commit_group;" ::: "memory"); }
__device__ __forceinline__ void cp_wait1()  { asm volatile("cp.async.wait_group 1;" ::: "memory"); }
__device__ __forceinline__ uint32_t f2tf(float f) {
    uint32_t u;
    asm("cvt.rna.tf32.f32 %0, %1;" : "=r"(u) : "f"(f));
    return u;
}
__device__ __forceinline__ float rndf(float f) { return __uint_as_float(f2tf(f)); }
__device__ __forceinline__ void mma8(float* c, const uint32_t* a, const uint32_t* b) {
    asm volatile(
        "mma.sync.aligned.m16n8k8.row.col.f32.tf32.tf32.f32 "
        "{%0,%1,%2,%3}, {%4,%5,%6,%7}, {%8,%9}, {%0,%1,%2,%3};"
        : "+f"(c[0]), "+f"(c[1]), "+f"(c[2]), "+f"(c[3])
        : "r"(a[0]), "r"(a[1]), "r"(a[2]), "r"(a[3]), "r"(b[0]), "r"(b[1]));
}

// ---------------- prep: concat+round weights, zero stats ----------------
__global__ void prep_k(const float* __restrict__ gw, const float* __restrict__ gb,
                       const float* __restrict__ tw, const float* __restrict__ tb,
                       const float* __restrict__ pw, const float* __restrict__ pb,
                       const float* __restrict__ ww)
{
    int i = blockIdx.x * 256 + threadIdx.x;
    const int per = CI * CIN;
    if (i < 3 * per) {
        int m = i / per, off = i - m * per;
        d_Wcat[i] = rndf((m == 0 ? tw : (m == 1 ? pw : gw))[off]);
    }
    if (i < CIN * CI) d_Wr[i] = rndf(ww[i]);
    if (i < CI)            d_Bcat[i] = tb[i];
    else if (i < 2 * CI)   d_Bcat[i] = pb[i - CI];
    else if (i < 3 * CI)   d_Bcat[i] = gb[i - 2 * CI];
    if (i < CIN) { d_Sum[i] = 0.f; d_Sq[i] = 0.f; }
}

// ================= tf32 mma.sync GEMM, 3-stage cp.async pipeline =================
// D[M,Npix] = alpha*A@op(B) (+bias)(+res), fp32 accum.
// A: [M,K] K-contig (pre-rounded tf32).
// B: TRANS_B ? [Npix,K] K-contig (out=A@B^T) : [K,Npix] pix-contig.
// Block tile 128x128, 128 threads (4 warps, 2x2 grid of 64x64 warp tiles), KTILE=32.
// LDS:MMA ratio 1.0 (32 LDS / 32 HMMA per warp per k8) -> ~10.2 FLOP/smem-byte.
// Smem/stage (floats): A 128x36, B TRANS? 128x36 : 32x136 (conflict-free pads).
template<bool TRANS_B, bool CVT_B, bool HAS_BIAS, bool HAS_RES, bool DO_STATS, bool ROUND_OUT>
__global__ void __launch_bounds__(128, 2) mma_gemm(
    int Npix, int KT, float alpha,
    const float* __restrict__ A,  int lda, long long sA,
    const float* __restrict__ Bm, int ldb, long long sB,
    float* __restrict__ C,        int ldc, long long sC,
    const float* __restrict__ bias,
    const float* __restrict__ res, long long sR)
{
    constexpr int ASZ = 128 * 36;                    // 4608 floats
    constexpr int BSZ = TRANS_B ? 128 * 36 : 32 * 136;
    constexpr int STG = ASZ + BSZ;
    extern __shared__ uint32_t sm[];
    const uint32_t smb = smem_u32(sm);

    const int tid = threadIdx.x;
    const int bz = blockIdx.z;
    A  += (long long)bz * sA;
    Bm += (long long)bz * sB;
    C  += (long long)bz * sC;
    const int rowA = blockIdx.y * 128;
    const int colB = blockIdx.x * 128;
    const int warp = tid >> 5, lane = tid & 31;
    const int wr = warp >> 1, wc = warp & 1;         // 2x2 warp grid, 64x64 tiles
    const int g = lane >> 2, q = lane & 3;

    float acc[4][8][4];
    #pragma unroll
    for (int i = 0; i < 4; i++)
        #pragma unroll
        for (int j = 0; j < 8; j++)
            #pragma unroll
            for (int k = 0; k < 4; k++) acc[i][j][k] = 0.f;

    auto load_tile = [&](int s, int kt) {
        const uint32_t baseA = smb + (uint32_t)(s * STG) * 4;
        #pragma unroll
        for (int j = 0; j < 8; j++) {                // A: 1024 16B chunks
            int u = tid + j * 128;
            int row = u >> 3, k16 = u & 7;
            cp16(baseA + (uint32_t)(row * 36 + k16 * 4) * 4,
                 A + (long long)(rowA + row) * lda + kt * 32 + k16 * 4, true);
        }
        const uint32_t baseB = baseA + ASZ * 4;
        #pragma unroll
        for (int j = 0; j < 8; j++) {                // B: 1024 16B chunks
            int u = tid + j * 128;
            if (TRANS_B) {
                int row = u >> 3, k16 = u & 7;
                bool ok = colB + row < Npix;
                cp16(baseB + (uint32_t)(row * 36 + k16 * 4) * 4,
                     Bm + (long long)(ok ? colB + row : 0) * ldb + kt * 32 + k16 * 4, ok);
            } else {
                int k = u >> 5, n16 = u & 31;
                int col = colB + n16 * 4;
                bool ok = col < Npix;
                cp16(baseB + (uint32_t)(k * 136 + n16 * 4) * 4,
                     Bm + (long long)(kt * 32 + k) * ldb + (ok ? col : 0), ok);
            }
        }
        cp_commit();
    };

    auto compute = [&](int s) {
        const uint32_t* As_ = sm + s * STG;
        const uint32_t* Bs_ = As_ + ASZ;
        #pragma unroll
        for (int k8 = 0; k8 < 4; k8++) {
            const int kb = k8 * 8;
            uint32_t af[4][4], bf[8][2];
            #pragma unroll
            for (int mt = 0; mt < 4; mt++) {
                int m0 = wr * 64 + mt * 16 + g;
                af[mt][0] = As_[m0 * 36 + kb + q];
                af[mt][1] = As_[(m0 + 8) * 36 + kb + q];
                af[mt][2] = As_[m0 * 36 + kb + q + 4];
                af[mt][3] = As_[(m0 + 8) * 36 + kb + q + 4];
            }
            #pragma unroll
            for (int nt = 0; nt < 8; nt++) {
                int n0 = wc * 64 + nt * 8 + g;
                uint32_t b0, b1;
                if (TRANS_B) {
                    b0 = Bs_[n0 * 36 + kb + q];
                    b1 = Bs_[n0 * 36 + kb + q + 4];
                } else {
                    b0 = Bs_[(kb + q) * 136 + n0];
                    b1 = Bs_[(kb + q + 4) * 136 + n0];
                }
                if (CVT_B) {
                    b0 = f2tf(__uint_as_float(b0));
                    b1 = f2tf(__uint_as_float(b1));
                }
                bf[nt][0] = b0; bf[nt][1] = b1;
            }
            #pragma unroll
            for (int mt = 0; mt < 4; mt++)
                #pragma unroll
                for (int nt = 0; nt < 8; nt++)
                    mma8(acc[mt][nt], af[mt], bf[nt]);
        }
    };

    // prologue: tiles 0,1 -> stages 0,1
    load_tile(0, 0);
    load_tile(1, 1);

    for (int kt = 0; kt < KT; kt++) {
        cp_wait1();                                  // tile kt resident
        __syncthreads();
        int lt = kt + 2;
        if (lt < KT) load_tile(lt % 3, lt);          // fills stage (kt-1)%3
        else cp_commit();                            // keep group count uniform
        compute(kt % 3);
    }

    // ---------------- epilogue ----------------
    float sumr[8], sqr[8];
    if (DO_STATS)
        #pragma unroll
        for (int i = 0; i < 8; i++) { sumr[i] = 0.f; sqr[i] = 0.f; }

    #pragma unroll
    for (int mt = 0; mt < 4; mt++) {
        const int r0 = rowA + wr * 64 + mt * 16 + g;
        const int r1 = r0 + 8;
        const float bv0 = HAS_BIAS ? bias[r0] : 0.f;
        const float bv1 = HAS_BIAS ? bias[r1] : 0.f;
        float* c0p = C + (long long)r0 * ldc;
        float* c1p = C + (long long)r1 * ldc;
        const float* rr0 = HAS_RES ? (res + (long long)bz * sR + (long long)r0 * ldc) : nullptr;
        const float* rr1 = HAS_RES ? (res + (long long)bz * sR + (long long)r1 * ldc) : nullptr;
        #pragma unroll
        for (int nt = 0; nt < 8; nt++) {
            const int col = colB + wc * 64 + nt * 8 + q * 2;
            if (col < Npix) {
                float v0 = acc[mt][nt][0] * alpha + bv0;
                float v1 = acc[mt][nt][1] * alpha + bv0;
                float v2 = acc[mt][nt][2] * alpha + bv1;
                float v3 = acc[mt][nt][3] * alpha + bv1;
                if (HAS_RES) {
                    float2 e0 = *(const float2*)(rr0 + col);
                    float2 e1 = *(const float2*)(rr1 + col);
                    v0 += e0.x; v1 += e0.y; v2 += e1.x; v3 += e1.y;
                }
                if (DO_STATS) {
                    sumr[2 * mt]     += v0 + v1;
                    sqr [2 * mt]     += v0 * v0 + v1 * v1;
                    sumr[2 * mt + 1] += v2 + v3;
                    sqr [2 * mt + 1] += v2 * v2 + v3 * v3;
                }
                if (ROUND_OUT) {
                    v0 = rndf(v0); v1 = rndf(v1); v2 = rndf(v2); v3 = rndf(v3);
                }
                *(float2*)(c0p + col) = make_float2(v0, v1);
                *(float2*)(c1p + col) = make_float2(v2, v3);
            }
        }
    }
    if (DO_STATS) {
        __syncthreads();
        float* sred = (float*)sm;
        sred[tid] = 0.f; sred[128 + tid] = 0.f;
        __syncthreads();
        #pragma unroll
        for (int i = 0; i < 8; i++) {
            int lr = wr * 64 + (i >> 1) * 16 + g + (i & 1) * 8;
            atomicAdd(&sred[lr], sumr[i]);
            atomicAdd(&sred[128 + lr], sqr[i]);
        }
        __syncthreads();
        atomicAdd(&d_Sum[rowA + tid], sred[tid]);
        atomicAdd(&d_Sq [rowA + tid], sred[128 + tid]);
    }
}

// ---------------- BN finalize / apply ----------------
__global__ void finalize_k(const float* __restrict__ gamma, const float* __restrict__ beta)
{
    int c = threadIdx.x;
    if (c < CIN) {
        const float cnt = (float)((long long)B_ * NPIX);
        float mean = d_Sum[c] / cnt;
        float var  = d_Sq[c] / cnt - mean * mean;
        float s = gamma[c] * rsqrtf(var + EPSV);
        d_Scale[c] = s;
        d_Shift[c] = beta[c] - mean * s;
    }
}

__global__ void apply_k(float* __restrict__ out)
{
    const long long n4 = (long long)B_ * CIN * NPIX / 4;
    const long long stride = (long long)gridDim.x * blockDim.x;
    for (long long i = (long long)blockIdx.x * blockDim.x + threadIdx.x; i < n4; i += stride) {
        int c = (int)((i / (NPIX / 4)) % CIN);
        float s = d_Scale[c], sh = d_Shift[c];
        float4 v = ((float4*)out)[i];
        v.x = v.x * s + sh; v.y = v.y * s + sh;
        v.z = v.z * s + sh; v.w = v.w * s + sh;
        ((float4*)out)[i] = v;
    }
}

// ---------------- launch ----------------
extern "C" void kernel_launch(void* const* d_in, const int* in_sizes, int n_in,
                              void* d_out, int out_size)
{
    const float* x       = (const float*)d_in[0];
    const float* g_w     = (const float*)d_in[1];
    const float* g_b     = (const float*)d_in[2];
    const float* theta_w = (const float*)d_in[3];
    const float* theta_b = (const float*)d_in[4];
    const float* phi_w   = (const float*)d_in[5];
    const float* phi_b   = (const float*)d_in[6];
    const float* W_w     = (const float*)d_in[7];
    const float* W_b     = (const float*)d_in[8];
    const float* gamma   = (const float*)d_in[9];
    const float* beta    = (const float*)d_in[10];
    float* out = (float*)d_out;

    float *tpg, *fbuf, *ybuf, *wcat, *bcat, *wr;
    cudaGetSymbolAddress((void**)&tpg,  d_TPG);
    cudaGetSymbolAddress((void**)&fbuf, d_F);
    cudaGetSymbolAddress((void**)&ybuf, d_Y);
    cudaGetSymbolAddress((void**)&wcat, d_Wcat);
    cudaGetSymbolAddress((void**)&bcat, d_Bcat);
    cudaGetSymbolAddress((void**)&wr,   d_Wr);

    const long long sX   = (long long)CIN * NPIX;
    const long long sTPG = (long long)3 * CI * NPIX;
    const long long sF   = (long long)CI * CI;
    const long long sY   = (long long)CI * NPIX;
    const int nBlk = (NPIX + 127) / 128;             // 25

    constexpr int STG_N = (128 * 36 + 32 * 136) * 4; // 35840 B
    constexpr int STG_T = (128 * 36 + 128 * 36) * 4; // 36864 B
    constexpr int SMEM_N = 3 * STG_N;                // 107520 (x2 CTA = 215040 <= 228KB)
    constexpr int SMEM_T = 3 * STG_T;                // 110592 (x2 CTA = 221184 <= 228KB)

    cudaFuncSetAttribute(mma_gemm<false, true,  true,  false, false, true >, cudaFuncAttributeMaxDynamicSharedMemorySize, SMEM_N);
    cudaFuncSetAttribute(mma_gemm<true,  false, false, false, false, true >, cudaFuncAttributeMaxDynamicSharedMemorySize, SMEM_T);
    cudaFuncSetAttribute(mma_gemm<false, false, false, false, false, true >, cudaFuncAttributeMaxDynamicSharedMemorySize, SMEM_N);
    cudaFuncSetAttribute(mma_gemm<false, false, true,  true,  true,  false>, cudaFuncAttributeMaxDynamicSharedMemorySize, SMEM_N);

    // 0) prep
    prep_k<<<(3 * CI * CIN + 255) / 256, 256>>>(g_w, g_b, theta_w, theta_b, phi_w, phi_b, W_w);

    // 1) theta|phi|g = Wcat[768,512] @ x[512,3136] + Bcat  (x unrounded -> CVT_B)
    mma_gemm<false, true, true, false, false, true><<<dim3(nBlk, 6, B_), 128, SMEM_N>>>(
        NPIX, CIN / 32, 1.f,
        wcat, CIN, 0,
        x, NPIX, sX,
        tpg, NPIX, sTPG,
        bcat, nullptr, 0);

    // 2) gram: f = theta @ phi^T / N   (both pre-rounded)
    mma_gemm<true, false, false, false, false, true><<<dim3(2, 2, B_), 128, SMEM_T>>>(
        CI, NPIX / 32, 1.f / (float)NPIX,
        tpg, NPIX, sTPG,
        tpg + (long long)CI * NPIX, NPIX, sTPG,
        fbuf, CI, sF,
        nullptr, nullptr, 0);

    // 3) y = f @ g  (both pre-rounded)
    mma_gemm<false, false, false, false, false, true><<<dim3(nBlk, 2, B_), 128, SMEM_N>>>(
        NPIX, CI / 32, 1.f,
        fbuf, CI, sF,
        tpg + (long long)2 * CI * NPIX, NPIX, sTPG,
        ybuf, NPIX, sY,
        nullptr, nullptr, 0);

    // 4) z = Wr @ y + W_b + x  (fused BN stats; full-precision output)
    mma_gemm<false, false, true, true, true, false><<<dim3(nBlk, 4, B_), 128, SMEM_N>>>(
        NPIX, CI / 32, 1.f,
        wr, CI, 0,
        ybuf, NPIX, sY,
        out, NPIX, sX,
        W_b, x, sX);

    // 5) BN finalize + apply
    finalize_k<<<1, 512>>>(gamma, beta);
    apply_k<<<2368, 256>>>(out);
}

// round 10
// speedup vs baseline: 1.1986x; 1.1986x over previous
#include <cuda_runtime.h>
#include <cuda_fp16.h>
#include <cstdint>

#define B_    32
#define CIN   512
#define CI    256
#define NPIX  3136
#define EPSV  1e-5f

// ---------------- scratch (static device globals; no allocation) ----------------
__device__ __align__(128) __half d_XT16[(size_t)B_ * NPIX * CIN];   // [b][pix][512]  x^T fp16
__device__ __align__(128) __half d_TPGT[(size_t)B_ * NPIX * 3*CI];  // [b][pix][768]  theta|phi|g ^T
__device__ __align__(128) __half d_TP  [(size_t)B_ * CIN * NPIX];   // [b][512][pix]  theta|phi (pix-contig)
__device__ __align__(128) __half d_F16 [(size_t)B_ * CI * CI];      // [b][256][256]
__device__ __align__(128) __half d_YT  [(size_t)B_ * NPIX * CI];    // [b][pix][256]  y^T
__device__ __align__(128) __half d_Wcat16[3 * CI * CIN];            // [768][512]
__device__ __align__(128) __half d_Wr16[CIN * CI];                  // [512][256]
__device__ float d_Bcat[3 * CI];
__device__ float d_Sum[CIN];
__device__ float d_Sq [CIN];
__device__ float d_Scale[CIN];
__device__ float d_Shift[CIN];

// ================= PTX helpers (sm_80+-portable) =================
__device__ __forceinline__ uint32_t smem_u32(const void* p) {
    uint32_t a;
    asm("{ .reg .u64 t; cvta.to.shared.u64 t, %1; cvt.u32.u64 %0, t; }" : "=r"(a) : "l"(p));
    return a;
}
__device__ __forceinline__ void cp16(uint32_t d, const void* s, bool ok) {
    int sz = ok ? 16 : 0;
    asm volatile("cp.async.cg.shared.global [%0], [%1], 16, %2;" :: "r"(d), "l"(s), "r"(sz) : "memory");
}
__device__ __forceinline__ void cp_commit() { asm volatile("cp.async.commit_group;" ::: "memory"); }
__device__ __forceinline__ void cp_wait2()  { asm volatile("cp.async.wait_group 2;" ::: "memory"); }
__device__ __forceinline__ void mma16(float* c, const uint32_t* a, const uint32_t* b) {
    asm volatile(
        "mma.sync.aligned.m16n8k16.row.col.f32.f16.f16.f32 "
        "{%0,%1,%2,%3}, {%4,%5,%6,%7}, {%8,%9}, {%0,%1,%2,%3};"
        : "+f"(c[0]), "+f"(c[1]), "+f"(c[2]), "+f"(c[3])
        : "r"(a[0]), "r"(a[1]), "r"(a[2]), "r"(a[3]), "r"(b[0]), "r"(b[1]));
}

// ---------------- prep: weights -> fp16, bias concat, zero stats ----------------
__global__ void prep_w(const float* __restrict__ gw, const float* __restrict__ gb,
                       const float* __restrict__ tw, const float* __restrict__ tb,
                       const float* __restrict__ pw, const float* __restrict__ pb,
                       const float* __restrict__ ww)
{
    int i = blockIdx.x * 256 + threadIdx.x;
    const int per = CI * CIN;
    if (i < 3 * per) {
        int m = i / per, off = i - m * per;
        d_Wcat16[i] = __float2half((m == 0 ? tw : (m == 1 ? pw : gw))[off]);
    }
    if (i < CIN * CI) d_Wr16[i] = __float2half(ww[i]);
    if (i < CI)            d_Bcat[i] = tb[i];
    else if (i < 2 * CI)   d_Bcat[i] = pb[i - CI];
    else if (i < 3 * CI)   d_Bcat[i] = gb[i - 2 * CI];
    if (i < CIN) { d_Sum[i] = 0.f; d_Sq[i] = 0.f; }
}

// ---------------- x [b][512][3136] fp32 -> xT16 [b][3136][512] fp16 ----------------
__global__ void xT_k(const float* __restrict__ x)
{
    __shared__ float t[32][33];
    const int p0 = blockIdx.x * 32, c0 = blockIdx.y * 32, b = blockIdx.z;
    const int tp = threadIdx.x & 31, tc = threadIdx.x >> 5;
    const float* xb = x + (size_t)b * CIN * NPIX;
    #pragma unroll
    for (int i = 0; i < 4; i++) {
        int cc = tc + i * 8;
        t[cc][tp] = xb[(size_t)(c0 + cc) * NPIX + p0 + tp];
    }
    __syncthreads();
    __half* o = d_XT16 + (size_t)b * NPIX * CIN;
    #pragma unroll
    for (int i = 0; i < 4; i++) {
        int pp = tc + i * 8;
        o[(size_t)(p0 + pp) * CIN + c0 + tp] = __float2half(t[tp][pp]);
    }
}

// ---------------- TPGT[:, :, 0:512] -> TP [b][512][3136] (pix-contig) ----------------
__global__ void t2_k()
{
    __shared__ __half t[32][33];
    const int p0 = blockIdx.x * 32, c0 = blockIdx.y * 32, b = blockIdx.z;
    const int tp = threadIdx.x & 31, tc = threadIdx.x >> 5;
    const __half* src = d_TPGT + (size_t)b * NPIX * (3 * CI);
    #pragma unroll
    for (int i = 0; i < 4; i++) {
        int pp = tc + i * 8;
        t[pp][tp] = src[(size_t)(p0 + pp) * (3 * CI) + c0 + tp];
    }
    __syncthreads();
    __half* o = d_TP + (size_t)b * CIN * NPIX;
    #pragma unroll
    for (int i = 0; i < 4; i++) {
        int cc = tc + i * 8;
        o[(size_t)(c0 + cc) * NPIX + p0 + tp] = t[tp][cc];
    }
}

// ================= fp16 mma.sync GEMM, 4-stage cp.async pipeline =================
// D[M, N] = alpha * A @ B^T (+bias[col]) ; A: [M,K] fp16 K-contig, B: [N,K] fp16 K-contig.
// OUT_F16: C fp16 [M][ldc] packed half2 stores.
// !OUT_F16 (G4): C fp32 written transposed C[col*ldc + row] + bias[col] + res + BN stats/col.
// Block 128x128, 256 thr (8 warps, 2x4 grid of 64x32 tiles), KTILE=32 (2 k16 steps).
// Smem rows padded to 40 halves (20 banks): frag LDS banks = 20g+q+c, conflict-free.
template<bool COL_BIAS, bool OUT_F16>
__global__ void __launch_bounds__(256, 2) gemm16(
    int Mtot, int KT, float alpha,
    const __half* __restrict__ A, int lda, long long sA,
    const __half* __restrict__ B, int ldb, long long sB,
    void* __restrict__ Cv, int ldc, long long sC,
    const float* __restrict__ bias,
    const float* __restrict__ res, long long sR)
{
    constexpr int STG32 = 2 * 128 * 20;              // 5120 u32 per stage (A+B)
    extern __shared__ uint32_t sm[];
    const uint32_t smb = smem_u32(sm);

    const int tid = threadIdx.x;
    const int bz = blockIdx.z;
    A += (long long)bz * sA;
    B += (long long)bz * sB;
    const int rowA = blockIdx.y * 128;
    const int colB = blockIdx.x * 128;
    const int warp = tid >> 5, lane = tid & 31;
    const int wr = warp >> 2, wc = warp & 3;         // 2x4 warp grid, 64x32 tiles
    const int g = lane >> 2, q = lane & 3;

    float acc[4][4][4];
    #pragma unroll
    for (int i = 0; i < 4; i++)
        #pragma unroll
        for (int j = 0; j < 4; j++)
            #pragma unroll
            for (int k = 0; k < 4; k++) acc[i][j][k] = 0.f;

    auto load_tile = [&](int s, int kt) {
        const uint32_t baseA = smb + (uint32_t)(s * STG32) * 4;
        #pragma unroll
        for (int j = 0; j < 2; j++) {                // A: 512 16B chunks
            int u = tid + j * 256;
            int row = u >> 2, c = u & 3;
            bool ok = rowA + row < Mtot;
            cp16(baseA + (uint32_t)(row * 20 + c * 4) * 4,
                 A + (size_t)(ok ? rowA + row : 0) * lda + kt * 32 + c * 8, ok);
        }
        const uint32_t baseB = baseA + 2560 * 4;
        #pragma unroll
        for (int j = 0; j < 2; j++) {                // B: 512 16B chunks (N exact)
            int u = tid + j * 256;
            int row = u >> 2, c = u & 3;
            cp16(baseB + (uint32_t)(row * 20 + c * 4) * 4,
                 B + (size_t)(colB + row) * ldb + kt * 32 + c * 8, true);
        }
        cp_commit();
    };

    auto compute = [&](int s) {
        const uint32_t* As_ = sm + s * STG32;
        const uint32_t* Bs_ = As_ + 2560;
        #pragma unroll
        for (int k16 = 0; k16 < 2; k16++) {
            const int ko = k16 * 8;
            uint32_t af[4][4], bf[4][2];
            #pragma unroll
            for (int mt = 0; mt < 4; mt++) {
                int m0 = wr * 64 + mt * 16 + g;
                af[mt][0] = As_[m0 * 20 + q + ko];
                af[mt][1] = As_[(m0 + 8) * 20 + q + ko];
                af[mt][2] = As_[m0 * 20 + q + 4 + ko];
                af[mt][3] = As_[(m0 + 8) * 20 + q + 4 + ko];
            }
            #pragma unroll
            for (int nt = 0; nt < 4; nt++) {
                int n0 = wc * 32 + nt * 8 + g;
                bf[nt][0] = Bs_[n0 * 20 + q + ko];
                bf[nt][1] = Bs_[n0 * 20 + q + 4 + ko];
            }
            #pragma unroll
            for (int mt = 0; mt < 4; mt++)
                #pragma unroll
                for (int nt = 0; nt < 4; nt++)
                    mma16(acc[mt][nt], af[mt], bf[nt]);
        }
    };

    // prologue: tiles 0,1,2
    load_tile(0, 0);
    load_tile(1, 1);
    load_tile(2, 2);

    for (int kt = 0; kt < KT; kt++) {
        cp_wait2();                                  // tile kt resident
        __syncthreads();
        int lt = kt + 3;
        if (lt < KT) load_tile(lt & 3, lt);
        else cp_commit();                            // keep group count uniform
        compute(kt & 3);
    }

    // ---------------- epilogue ----------------
    if (OUT_F16) {
        __half* C = ((__half*)Cv) + (long long)bz * sC;
        #pragma unroll
        for (int mt = 0; mt < 4; mt++) {
            const int r0 = rowA + wr * 64 + mt * 16 + g;
            const int r1 = r0 + 8;
            #pragma unroll
            for (int nt = 0; nt < 4; nt++) {
                const int col = colB + wc * 32 + nt * 8 + 2 * q;
                float v0 = acc[mt][nt][0] * alpha;
                float v1 = acc[mt][nt][1] * alpha;
                float v2 = acc[mt][nt][2] * alpha;
                float v3 = acc[mt][nt][3] * alpha;
                if (COL_BIAS) {
                    float b0 = bias[col], b1 = bias[col + 1];
                    v0 += b0; v1 += b1; v2 += b0; v3 += b1;
                }
                if (r0 < Mtot) *(__half2*)(C + (size_t)r0 * ldc + col) = __floats2half2_rn(v0, v1);
                if (r1 < Mtot) *(__half2*)(C + (size_t)r1 * ldc + col) = __floats2half2_rn(v2, v3);
            }
        }
    } else {
        // G4: transposed fp32 out + residual + per-col BN stats
        float* C = ((float*)Cv) + (long long)bz * sC;
        const float* R = res + (long long)bz * sR;
        float sc[8], sq[8];
        #pragma unroll
        for (int i = 0; i < 8; i++) { sc[i] = 0.f; sq[i] = 0.f; }
        #pragma unroll
        for (int mt = 0; mt < 4; mt++) {
            const int r0 = rowA + wr * 64 + mt * 16 + g;
            const int r1 = r0 + 8;
            #pragma unroll
            for (int nt = 0; nt < 4; nt++) {
                #pragma unroll
                for (int j = 0; j < 2; j++) {
                    const int col = colB + wc * 32 + nt * 8 + 2 * q + j;
                    const float bv = bias[col];
                    const size_t base = (size_t)col * ldc;
                    if (r0 < Mtot) {
                        float v = acc[mt][nt][j] + bv + R[base + r0];
                        C[base + r0] = v;
                        sc[nt * 2 + j] += v; sq[nt * 2 + j] += v * v;
                    }
                    if (r1 < Mtot) {
                        float v = acc[mt][nt][2 + j] + bv + R[base + r1];
                        C[base + r1] = v;
                        sc[nt * 2 + j] += v; sq[nt * 2 + j] += v * v;
                    }
                }
            }
        }
        __syncthreads();
        float* sred = (float*)sm;
        if (tid < 128) { sred[tid] = 0.f; sred[128 + tid] = 0.f; }
        __syncthreads();
        #pragma unroll
        for (int nt = 0; nt < 4; nt++)
            #pragma unroll
            for (int j = 0; j < 2; j++) {
                int cib = wc * 32 + nt * 8 + 2 * q + j;
                atomicAdd(&sred[cib], sc[nt * 2 + j]);
                atomicAdd(&sred[128 + cib], sq[nt * 2 + j]);
            }
        __syncthreads();
        if (tid < 128) {
            atomicAdd(&d_Sum[colB + tid], sred[tid]);
            atomicAdd(&d_Sq [colB + tid], sred[128 + tid]);
        }
    }
}

// ---------------- BN finalize / apply ----------------
__global__ void finalize_k(const float* __restrict__ gamma, const float* __restrict__ beta)
{
    int c = threadIdx.x;
    if (c < CIN) {
        const float cnt = (float)((long long)B_ * NPIX);
        float mean = d_Sum[c] / cnt;
        float var  = d_Sq[c] / cnt - mean * mean;
        float s = gamma[c] * rsqrtf(var + EPSV);
        d_Scale[c] = s;
        d_Shift[c] = beta[c] - mean * s;
    }
}

__global__ void apply_k(float* __restrict__ out)
{
    const long long n4 = (long long)B_ * CIN * NPIX / 4;
    const long long stride = (long long)gridDim.x * blockDim.x;
    for (long long i = (long long)blockIdx.x * blockDim.x + threadIdx.x; i < n4; i += stride) {
        int c = (int)((i / (NPIX / 4)) % CIN);
        float s = d_Scale[c], sh = d_Shift[c];
        float4 v = ((float4*)out)[i];
        v.x = v.x * s + sh; v.y = v.y * s + sh;
        v.z = v.z * s + sh; v.w = v.w * s + sh;
        ((float4*)out)[i] = v;
    }
}

// ---------------- launch ----------------
extern "C" void kernel_launch(void* const* d_in, const int* in_sizes, int n_in,
                              void* d_out, int out_size)
{
    const float* x       = (const float*)d_in[0];
    const float* g_w     = (const float*)d_in[1];
    const float* g_b     = (const float*)d_in[2];
    const float* theta_w = (const float*)d_in[3];
    const float* theta_b = (const float*)d_in[4];
    const float* phi_w   = (const float*)d_in[5];
    const float* phi_b   = (const float*)d_in[6];
    const float* W_w     = (const float*)d_in[7];
    const float* W_b     = (const float*)d_in[8];
    const float* gamma   = (const float*)d_in[9];
    const float* beta    = (const float*)d_in[10];
    float* out = (float*)d_out;

    __half *xt, *tpgt, *tp, *f16, *yt, *wc16, *wr16;
    float *bcat;
    cudaGetSymbolAddress((void**)&xt,   d_XT16);
    cudaGetSymbolAddress((void**)&tpgt, d_TPGT);
    cudaGetSymbolAddress((void**)&tp,   d_TP);
    cudaGetSymbolAddress((void**)&f16,  d_F16);
    cudaGetSymbolAddress((void**)&yt,   d_YT);
    cudaGetSymbolAddress((void**)&wc16, d_Wcat16);
    cudaGetSymbolAddress((void**)&wr16, d_Wr16);
    cudaGetSymbolAddress((void**)&bcat, d_Bcat);

    constexpr int SMEM = 4 * 5120 * 4;               // 81920 B
    cudaFuncSetAttribute(gemm16<true,  true >, cudaFuncAttributeMaxDynamicSharedMemorySize, SMEM);
    cudaFuncSetAttribute(gemm16<false, true >, cudaFuncAttributeMaxDynamicSharedMemorySize, SMEM);
    cudaFuncSetAttribute(gemm16<true,  false>, cudaFuncAttributeMaxDynamicSharedMemorySize, SMEM);

    const long long sX   = (long long)CIN * NPIX;       // x / out per batch
    const long long sXT  = (long long)NPIX * CIN;
    const long long sTPG = (long long)NPIX * 3 * CI;
    const long long sTP  = (long long)CIN * NPIX;
    const long long sF   = (long long)CI * CI;
    const long long sYT  = (long long)NPIX * CI;

    // 0) prep weights + x transpose
    prep_w<<<1536, 256>>>(g_w, g_b, theta_w, theta_b, phi_w, phi_b, W_w);
    xT_k<<<dim3(98, 16, B_), 256>>>(x);

    // 1) TPGT[pix][768] = xT16[pix][512k] @ Wcat16[768][512k]^T + Bcat[col]
    gemm16<true, true><<<dim3(6, 25, B_), 256, SMEM>>>(
        NPIX, CIN / 32, 1.f,
        xt, CIN, sXT,
        wc16, CIN, 0,
        tpgt, 3 * CI, sTPG,
        bcat, nullptr, 0);

    // 1b) transpose theta|phi cols -> TP [512][pix]
    t2_k<<<dim3(98, 16, B_), 256>>>();

    // 2) f[c][d] = theta[c][pix-k] @ phi[d][pix-k]^T / N
    gemm16<false, true><<<dim3(2, 2, B_), 256, SMEM>>>(
        CI, NPIX / 32, 1.f / (float)NPIX,
        tp, NPIX, sTP,
        tp + (long long)CI * NPIX, NPIX, sTP,
        f16, CI, sF,
        nullptr, nullptr, 0);

    // 3) yT[pix][c] = gT[pix][256k] @ f[c][256k]^T   (gT = TPGT cols 512..767)
    gemm16<false, true><<<dim3(2, 25, B_), 256, SMEM>>>(
        NPIX, CI / 32, 1.f,
        tpgt + 2 * CI, 3 * CI, sTPG,
        f16, CI, sF,
        yt, CI, sYT,
        nullptr, nullptr, 0);

    // 4) z^T = yT[pix][256k] @ Wr16[512co][256k]^T; write transposed fp32 + x + W_b + stats
    gemm16<true, false><<<dim3(4, 25, B_), 256, SMEM>>>(
        NPIX, CI / 32, 1.f,
        yt, CI, sYT,
        wr16, CI, 0,
        out, NPIX, sX,
        W_b, x, sX);

    // 5) BN finalize + apply
    finalize_k<<<1, 512>>>(gamma, beta);
    apply_k<<<2368, 256>>>(out);
}

// round 12
// speedup vs baseline: 1.2395x; 1.0341x over previous
#include <cuda_runtime.h>
#include <cuda_fp16.h>
#include <cstdint>

#define B_    32
#define CIN   512
#define CI    256
#define NPIX  3136
#define EPSV  1e-5f

// ---------------- scratch (static device globals; no allocation) ----------------
__device__ __align__(128) __half d_XT16[(size_t)B_ * NPIX * CIN];   // [b][pix][512]  x^T fp16
__device__ __align__(128) __half d_TPGT[(size_t)B_ * NPIX * 3*CI];  // [b][pix][768]  theta|phi|g ^T
__device__ __align__(128) __half d_TP  [(size_t)B_ * CIN * NPIX];   // [b][512][pix]  theta|phi (pix-contig)
__device__ __align__(128) __half d_F16 [(size_t)B_ * CI * CI];      // [b][256][256]
__device__ __align__(128) __half d_YT  [(size_t)B_ * NPIX * CI];    // [b][pix][256]  y^T
__device__ __align__(128) __half d_Wcat16[3 * CI * CIN];            // [768][512]
__device__ __align__(128) __half d_Wr16[CIN * CI];                  // [512][256]
__device__ float d_Bcat[3 * CI];
__device__ float d_Sum[CIN];
__device__ float d_Sq [CIN];
__device__ float d_Scale[CIN];
__device__ float d_Shift[CIN];

// ================= PTX helpers (sm_80+-portable) =================
__device__ __forceinline__ uint32_t smem_u32(const void* p) {
    uint32_t a;
    asm("{ .reg .u64 t; cvta.to.shared.u64 t, %1; cvt.u32.u64 %0, t; }" : "=r"(a) : "l"(p));
    return a;
}
__device__ __forceinline__ void cp16(uint32_t d, const void* s, bool ok) {
    int sz = ok ? 16 : 0;
    asm volatile("cp.async.cg.shared.global [%0], [%1], 16, %2;" :: "r"(d), "l"(s), "r"(sz) : "memory");
}
__device__ __forceinline__ void cp_commit() { asm volatile("cp.async.commit_group;" ::: "memory"); }
__device__ __forceinline__ void cp_wait2()  { asm volatile("cp.async.wait_group 2;" ::: "memory"); }
__device__ __forceinline__ void mma16(float* c, const uint32_t* a, const uint32_t* b) {
    asm volatile(
        "mma.sync.aligned.m16n8k16.row.col.f32.f16.f16.f32 "
        "{%0,%1,%2,%3}, {%4,%5,%6,%7}, {%8,%9}, {%0,%1,%2,%3};"
        : "+f"(c[0]), "+f"(c[1]), "+f"(c[2]), "+f"(c[3])
        : "r"(a[0]), "r"(a[1]), "r"(a[2]), "r"(a[3]), "r"(b[0]), "r"(b[1]));
}

// ---------------- prep: weights -> fp16, bias concat, zero stats ----------------
__global__ void prep_w(const float* __restrict__ gw, const float* __restrict__ gb,
                       const float* __restrict__ tw, const float* __restrict__ tb,
                       const float* __restrict__ pw, const float* __restrict__ pb,
                       const float* __restrict__ ww)
{
    int i = blockIdx.x * 256 + threadIdx.x;
    const int per = CI * CIN;
    if (i < 3 * per) {
        int m = i / per, off = i - m * per;
        d_Wcat16[i] = __float2half((m == 0 ? tw : (m == 1 ? pw : gw))[off]);
    }
    if (i < CIN * CI) d_Wr16[i] = __float2half(ww[i]);
    if (i < CI)            d_Bcat[i] = tb[i];
    else if (i < 2 * CI)   d_Bcat[i] = pb[i - CI];
    else if (i < 3 * CI)   d_Bcat[i] = gb[i - 2 * CI];
    if (i < CIN) { d_Sum[i] = 0.f; d_Sq[i] = 0.f; }
}

// ---------------- x [b][512][3136] fp32 -> xT16 [b][3136][512] fp16 (64x64 tiles) ----
__global__ void xT_k(const float* __restrict__ x)
{
    __shared__ __half t[64][66];
    const int tid = threadIdx.x;
    const int p0 = blockIdx.x * 64, c0 = blockIdx.y * 64, b = blockIdx.z;
    const float* xb = x + (size_t)b * CIN * NPIX;
    // load: 4 passes, 16 ch rows each; thread reads float4 = 4 pix (scalar smem writes)
    #pragma unroll
    for (int ps = 0; ps < 4; ps++) {
        int ch = (tid >> 4) + ps * 16;
        int px = (tid & 15) * 4;
        float4 v = *(const float4*)(xb + (size_t)(c0 + ch) * NPIX + p0 + px);
        t[ch][px + 0] = __float2half(v.x);
        t[ch][px + 1] = __float2half(v.y);
        t[ch][px + 2] = __float2half(v.z);
        t[ch][px + 3] = __float2half(v.w);
    }
    __syncthreads();
    // write: 2 passes, 32 pix rows each; thread gathers 8 ch (scalar) -> 16B global store
    __half* o = d_XT16 + (size_t)b * NPIX * CIN;
    #pragma unroll
    for (int ps = 0; ps < 2; ps++) {
        int px = (tid >> 3) + ps * 32;
        int cc = (tid & 7) * 8;
        __half v[8];
        #pragma unroll
        for (int i = 0; i < 8; i++) v[i] = t[cc + i][px];
        *(uint4*)(o + (size_t)(p0 + px) * CIN + c0 + cc) = *(uint4*)v;
    }
}

// ---------------- TPGT[:, :, 0:512] -> TP [b][512][pix] (64x64 tiles, 16B I/O) ----
// Row stride 72 halves = 144 B (multiple of 16) so uint4 smem stores are aligned.
__global__ void t2_k()
{
    __shared__ __half t[64][72];
    const int tid = threadIdx.x;
    const int p0 = blockIdx.x * 64, c0 = blockIdx.y * 64, b = blockIdx.z;
    const __half* src = d_TPGT + (size_t)b * NPIX * (3 * CI);
    // load: 2 passes, 32 pix rows each; thread reads 8 ch = 16B -> aligned uint4 smem store
    #pragma unroll
    for (int ps = 0; ps < 2; ps++) {
        int p = (tid >> 3) + ps * 32;
        int c = (tid & 7) * 8;
        *(uint4*)&t[p][c] = *(const uint4*)(src + (size_t)(p0 + p) * (3 * CI) + c0 + c);
    }
    __syncthreads();
    // write: 2 passes, 32 ch rows each; thread gathers 8 pix (scalar) -> 16B global store
    __half* o = d_TP + (size_t)b * CIN * NPIX;
    #pragma unroll
    for (int ps = 0; ps < 2; ps++) {
        int c = (tid >> 3) + ps * 32;
        int px = (tid & 7) * 8;
        __half v[8];
        #pragma unroll
        for (int i = 0; i < 8; i++) v[i] = t[px + i][c];
        *(uint4*)(o + (size_t)(c0 + c) * NPIX + p0 + px) = *(uint4*)v;
    }
}

// ================= fp16 mma.sync GEMM, 4-stage cp.async pipeline =================
// D[M, N] = alpha * A @ B^T ; A: [M,K] fp16 K-contig, B: [N,K] fp16 K-contig.
// OUT_F16: C fp16 [M][ldc], optional per-col bias.
// !OUT_F16 (G4): C fp32 [M][ldc] row-major + per-row bias + residual + per-row BN stats.
// Block 128x128, 256 thr (8 warps, 2x4 grid of 64x32 tiles), KTILE=32 (2 k16 steps).
template<bool COL_BIAS, bool OUT_F16>
__global__ void __launch_bounds__(256, 2) gemm16(
    int Mtot, int Ntot, int KT, float alpha,
    const __half* __restrict__ A, int lda, long long sA,
    const __half* __restrict__ B, int ldb, long long sB,
    void* __restrict__ Cv, int ldc, long long sC,
    const float* __restrict__ bias,
    const float* __restrict__ res, long long sR)
{
    constexpr int STG32 = 2 * 128 * 20;              // 5120 u32 per stage (A+B)
    extern __shared__ uint32_t sm[];
    const uint32_t smb = smem_u32(sm);

    const int tid = threadIdx.x;
    const int bz = blockIdx.z;
    A += (long long)bz * sA;
    B += (long long)bz * sB;
    const int rowA = blockIdx.y * 128;
    const int colB = blockIdx.x * 128;
    const int warp = tid >> 5, lane = tid & 31;
    const int wr = warp >> 2, wc = warp & 3;         // 2x4 warp grid, 64x32 tiles
    const int g = lane >> 2, q = lane & 3;

    float acc[4][4][4];
    #pragma unroll
    for (int i = 0; i < 4; i++)
        #pragma unroll
        for (int j = 0; j < 4; j++)
            #pragma unroll
            for (int k = 0; k < 4; k++) acc[i][j][k] = 0.f;

    auto load_tile = [&](int s, int kt) {
        const uint32_t baseA = smb + (uint32_t)(s * STG32) * 4;
        #pragma unroll
        for (int j = 0; j < 2; j++) {                // A: 512 16B chunks
            int u = tid + j * 256;
            int row = u >> 2, c = u & 3;
            bool ok = rowA + row < Mtot;
            cp16(baseA + (uint32_t)(row * 20 + c * 4) * 4,
                 A + (size_t)(ok ? rowA + row : 0) * lda + kt * 32 + c * 8, ok);
        }
        const uint32_t baseB = baseA + 2560 * 4;
        #pragma unroll
        for (int j = 0; j < 2; j++) {                // B: 512 16B chunks
            int u = tid + j * 256;
            int row = u >> 2, c = u & 3;
            bool ok = colB + row < Ntot;
            cp16(baseB + (uint32_t)(row * 20 + c * 4) * 4,
                 B + (size_t)(ok ? colB + row : 0) * ldb + kt * 32 + c * 8, ok);
        }
        cp_commit();
    };

    auto compute = [&](int s) {
        const uint32_t* As_ = sm + s * STG32;
        const uint32_t* Bs_ = As_ + 2560;
        #pragma unroll
        for (int k16 = 0; k16 < 2; k16++) {
            const int ko = k16 * 8;
            uint32_t af[4][4], bf[4][2];
            #pragma unroll
            for (int mt = 0; mt < 4; mt++) {
                int m0 = wr * 64 + mt * 16 + g;
                af[mt][0] = As_[m0 * 20 + q + ko];
                af[mt][1] = As_[(m0 + 8) * 20 + q + ko];
                af[mt][2] = As_[m0 * 20 + q + 4 + ko];
                af[mt][3] = As_[(m0 + 8) * 20 + q + 4 + ko];
            }
            #pragma unroll
            for (int nt = 0; nt < 4; nt++) {
                int n0 = wc * 32 + nt * 8 + g;
                bf[nt][0] = Bs_[n0 * 20 + q + ko];
                bf[nt][1] = Bs_[n0 * 20 + q + 4 + ko];
            }
            #pragma unroll
            for (int mt = 0; mt < 4; mt++)
                #pragma unroll
                for (int nt = 0; nt < 4; nt++)
                    mma16(acc[mt][nt], af[mt], bf[nt]);
        }
    };

    // prologue: tiles 0,1,2
    load_tile(0, 0);
    load_tile(1, 1);
    load_tile(2, 2);

    for (int kt = 0; kt < KT; kt++) {
        cp_wait2();                                  // tile kt resident
        __syncthreads();
        int lt = kt + 3;
        if (lt < KT) load_tile(lt & 3, lt);
        else cp_commit();                            // keep group count uniform
        compute(kt & 3);
    }

    // ---------------- epilogue ----------------
    if (OUT_F16) {
        __half* C = ((__half*)Cv) + (long long)bz * sC;
        #pragma unroll
        for (int mt = 0; mt < 4; mt++) {
            const int r0 = rowA + wr * 64 + mt * 16 + g;
            const int r1 = r0 + 8;
            #pragma unroll
            for (int nt = 0; nt < 4; nt++) {
                const int col = colB + wc * 32 + nt * 8 + 2 * q;
                if (col >= Ntot) continue;
                float v0 = acc[mt][nt][0] * alpha;
                float v1 = acc[mt][nt][1] * alpha;
                float v2 = acc[mt][nt][2] * alpha;
                float v3 = acc[mt][nt][3] * alpha;
                if (COL_BIAS) {
                    float b0 = bias[col], b1 = bias[col + 1];
                    v0 += b0; v1 += b1; v2 += b0; v3 += b1;
                }
                if (r0 < Mtot) *(__half2*)(C + (size_t)r0 * ldc + col) = __floats2half2_rn(v0, v1);
                if (r1 < Mtot) *(__half2*)(C + (size_t)r1 * ldc + col) = __floats2half2_rn(v2, v3);
            }
        }
    } else {
        // G4: row-major fp32 out + per-row bias + residual + per-row BN stats
        float* C = ((float*)Cv) + (long long)bz * sC;
        const float* R = res + (long long)bz * sR;
        float sumr[8], sqr[8];
        #pragma unroll
        for (int i = 0; i < 8; i++) { sumr[i] = 0.f; sqr[i] = 0.f; }

        #pragma unroll
        for (int mt = 0; mt < 4; mt++) {
            const int r0 = rowA + wr * 64 + mt * 16 + g;
            const int r1 = r0 + 8;
            const float bv0 = bias[r0];
            const float bv1 = bias[r1];
            float* c0p = C + (size_t)r0 * ldc;
            float* c1p = C + (size_t)r1 * ldc;
            const float* rr0 = R + (size_t)r0 * ldc;
            const float* rr1 = R + (size_t)r1 * ldc;
            #pragma unroll
            for (int nt = 0; nt < 4; nt++) {
                const int col = colB + wc * 32 + nt * 8 + 2 * q;
                if (col < Ntot) {
                    float2 e0 = *(const float2*)(rr0 + col);
                    float2 e1 = *(const float2*)(rr1 + col);
                    float v0 = acc[mt][nt][0] + bv0 + e0.x;
                    float v1 = acc[mt][nt][1] + bv0 + e0.y;
                    float v2 = acc[mt][nt][2] + bv1 + e1.x;
                    float v3 = acc[mt][nt][3] + bv1 + e1.y;
                    *(float2*)(c0p + col) = make_float2(v0, v1);
                    *(float2*)(c1p + col) = make_float2(v2, v3);
                    sumr[2 * mt]     += v0 + v1;
                    sqr [2 * mt]     += v0 * v0 + v1 * v1;
                    sumr[2 * mt + 1] += v2 + v3;
                    sqr [2 * mt + 1] += v2 * v2 + v3 * v3;
                }
            }
        }
        __syncthreads();
        float* sred = (float*)sm;
        if (tid < 128) { sred[tid] = 0.f; sred[128 + tid] = 0.f; }
        __syncthreads();
        #pragma unroll
        for (int i = 0; i < 8; i++) {
            int lr = wr * 64 + (i >> 1) * 16 + g + (i & 1) * 8;
            atomicAdd(&sred[lr], sumr[i]);
            atomicAdd(&sred[128 + lr], sqr[i]);
        }
        __syncthreads();
        if (tid < 128) {
            atomicAdd(&d_Sum[rowA + tid], sred[tid]);
            atomicAdd(&d_Sq [rowA + tid], sred[128 + tid]);
        }
    }
}

// ---------------- BN finalize / apply ----------------
__global__ void finalize_k(const float* __restrict__ gamma, const float* __restrict__ beta)
{
    int c = threadIdx.x;
    if (c < CIN) {
        const float cnt = (float)((long long)B_ * NPIX);
        float mean = d_Sum[c] / cnt;
        float var  = d_Sq[c] / cnt - mean * mean;
        float s = gamma[c] * rsqrtf(var + EPSV);
        d_Scale[c] = s;
        d_Shift[c] = beta[c] - mean * s;
    }
}

__global__ void apply_k(float* __restrict__ out)
{
    const long long n4 = (long long)B_ * CIN * NPIX / 4;
    const long long stride = (long long)gridDim.x * blockDim.x;
    for (long long i = (long long)blockIdx.x * blockDim.x + threadIdx.x; i < n4; i += stride) {
        int c = (int)((i / (NPIX / 4)) % CIN);
        float s = d_Scale[c], sh = d_Shift[c];
        float4 v = ((float4*)out)[i];
        v.x = v.x * s + sh; v.y = v.y * s + sh;
        v.z = v.z * s + sh; v.w = v.w * s + sh;
        ((float4*)out)[i] = v;
    }
}

// ---------------- launch ----------------
extern "C" void kernel_launch(void* const* d_in, const int* in_sizes, int n_in,
                              void* d_out, int out_size)
{
    const float* x       = (const float*)d_in[0];
    const float* g_w     = (const float*)d_in[1];
    const float* g_b     = (const float*)d_in[2];
    const float* theta_w = (const float*)d_in[3];
    const float* theta_b = (const float*)d_in[4];
    const float* phi_w   = (const float*)d_in[5];
    const float* phi_b   = (const float*)d_in[6];
    const float* W_w     = (const float*)d_in[7];
    const float* W_b     = (const float*)d_in[8];
    const float* gamma   = (const float*)d_in[9];
    const float* beta    = (const float*)d_in[10];
    float* out = (float*)d_out;

    __half *xt, *tpgt, *tp, *f16, *yt, *wc16, *wr16;
    float *bcat;
    cudaGetSymbolAddress((void**)&xt,   d_XT16);
    cudaGetSymbolAddress((void**)&tpgt, d_TPGT);
    cudaGetSymbolAddress((void**)&tp,   d_TP);
    cudaGetSymbolAddress((void**)&f16,  d_F16);
    cudaGetSymbolAddress((void**)&yt,   d_YT);
    cudaGetSymbolAddress((void**)&wc16, d_Wcat16);
    cudaGetSymbolAddress((void**)&wr16, d_Wr16);
    cudaGetSymbolAddress((void**)&bcat, d_Bcat);

    constexpr int SMEM = 4 * 5120 * 4;               // 81920 B
    cudaFuncSetAttribute(gemm16<true,  true >, cudaFuncAttributeMaxDynamicSharedMemorySize, SMEM);
    cudaFuncSetAttribute(gemm16<false, true >, cudaFuncAttributeMaxDynamicSharedMemorySize, SMEM);
    cudaFuncSetAttribute(gemm16<false, false>, cudaFuncAttributeMaxDynamicSharedMemorySize, SMEM);

    const long long sX   = (long long)CIN * NPIX;       // x / out per batch
    const long long sXT  = (long long)NPIX * CIN;
    const long long sTPG = (long long)NPIX * 3 * CI;
    const long long sTP  = (long long)CIN * NPIX;
    const long long sF   = (long long)CI * CI;
    const long long sYT  = (long long)NPIX * CI;

    // 0) prep weights + x transpose (49x64 = 3136 exact)
    prep_w<<<1536, 256>>>(g_w, g_b, theta_w, theta_b, phi_w, phi_b, W_w);
    xT_k<<<dim3(49, 8, B_), 256>>>(x);

    // 1) TPGT[pix][768] = xT16[pix][512k] @ Wcat16[768][512k]^T + Bcat[col]
    gemm16<true, true><<<dim3(6, 25, B_), 256, SMEM>>>(
        NPIX, 3 * CI, CIN / 32, 1.f,
        xt, CIN, sXT,
        wc16, CIN, 0,
        tpgt, 3 * CI, sTPG,
        bcat, nullptr, 0);

    // 1b) transpose theta|phi cols -> TP [512][pix]
    t2_k<<<dim3(49, 8, B_), 256>>>();

    // 2) f[c][d] = theta[c][pix-k] @ phi[d][pix-k]^T / N
    gemm16<false, true><<<dim3(2, 2, B_), 256, SMEM>>>(
        CI, CI, NPIX / 32, 1.f / (float)NPIX,
        tp, NPIX, sTP,
        tp + (long long)CI * NPIX, NPIX, sTP,
        f16, CI, sF,
        nullptr, nullptr, 0);

    // 3) yT[pix][c] = gT[pix][256k] @ f[c][256k]^T   (gT = TPGT cols 512..767)
    gemm16<false, true><<<dim3(2, 25, B_), 256, SMEM>>>(
        NPIX, CI, CI / 32, 1.f,
        tpgt + 2 * CI, 3 * CI, sTPG,
        f16, CI, sF,
        yt, CI, sYT,
        nullptr, nullptr, 0);

    // 4) z[ch][pix] = Wr16[512ch][256k] @ yT[pix][256k]^T + W_b[ch] + x  (row stats)
    gemm16<false, false><<<dim3(25, 4, B_), 256, SMEM>>>(
        CIN, NPIX, CI / 32, 1.f,
        wr16, CI, 0,
        yt, CI, sYT,
        out, NPIX, sX,
        W_b, x, sX);

    // 5) BN finalize + apply
    finalize_k<<<1, 512>>>(gamma, beta);
    apply_k<<<2368, 256>>>(out);
}

// round 13
// speedup vs baseline: 1.2918x; 1.0422x over previous
#include <cuda_runtime.h>
#include <cuda_fp16.h>
#include <cstdint>

#define B_    32
#define CIN   512
#define CI    256
#define NPIX  3136
#define EPSV  1e-5f

// ---------------- scratch (static device globals; no allocation) ----------------
__device__ __align__(128) __half d_XT16[(size_t)B_ * NPIX * CIN];   // [b][pix][512]  x^T fp16
__device__ __align__(128) __half d_TPGT[(size_t)B_ * NPIX * 3*CI];  // [b][pix][768]  theta|phi|g ^T
__device__ __align__(128) __half d_TP  [(size_t)B_ * CIN * NPIX];   // [b][512][pix]  theta|phi (pix-contig)
__device__ __align__(128) __half d_F16 [(size_t)B_ * CI * CI];      // [b][256][256]
__device__ __align__(128) __half d_YT  [(size_t)B_ * NPIX * CI];    // [b][pix][256]  y^T
__device__ __align__(128) __half d_Wcat16[3 * CI * CIN];            // [768][512]
__device__ __align__(128) __half d_Wr16[CIN * CI];                  // [512][256]
__device__ __align__(128) float d_GP[(size_t)4 * B_ * CI * CI];     // G2 split-K partials
__device__ float d_Bcat[3 * CI];
__device__ float d_Sum[CIN];
__device__ float d_Sq [CIN];
__device__ float d_Scale[CIN];
__device__ float d_Shift[CIN];

// ================= PTX helpers (sm_80+-portable) =================
__device__ __forceinline__ uint32_t smem_u32(const void* p) {
    uint32_t a;
    asm("{ .reg .u64 t; cvta.to.shared.u64 t, %1; cvt.u32.u64 %0, t; }" : "=r"(a) : "l"(p));
    return a;
}
__device__ __forceinline__ void cp16(uint32_t d, const void* s, bool ok) {
    int sz = ok ? 16 : 0;
    asm volatile("cp.async.cg.shared.global [%0], [%1], 16, %2;" :: "r"(d), "l"(s), "r"(sz) : "memory");
}
__device__ __forceinline__ void cp_commit() { asm volatile("cp.async.commit_group;" ::: "memory"); }
__device__ __forceinline__ void cp_wait2()  { asm volatile("cp.async.wait_group 2;" ::: "memory"); }
__device__ __forceinline__ void mma16(float* c, const uint32_t* a, const uint32_t* b) {
    asm volatile(
        "mma.sync.aligned.m16n8k16.row.col.f32.f16.f16.f32 "
        "{%0,%1,%2,%3}, {%4,%5,%6,%7}, {%8,%9}, {%0,%1,%2,%3};"
        : "+f"(c[0]), "+f"(c[1]), "+f"(c[2]), "+f"(c[3])
        : "r"(a[0]), "r"(a[1]), "r"(a[2]), "r"(a[3]), "r"(b[0]), "r"(b[1]));
}

// ---------------- prep: weights -> fp16, bias concat, zero stats ----------------
__global__ void prep_w(const float* __restrict__ gw, const float* __restrict__ gb,
                       const float* __restrict__ tw, const float* __restrict__ tb,
                       const float* __restrict__ pw, const float* __restrict__ pb,
                       const float* __restrict__ ww)
{
    int i = blockIdx.x * 256 + threadIdx.x;
    const int per = CI * CIN;
    if (i < 3 * per) {
        int m = i / per, off = i - m * per;
        d_Wcat16[i] = __float2half((m == 0 ? tw : (m == 1 ? pw : gw))[off]);
    }
    if (i < CIN * CI) d_Wr16[i] = __float2half(ww[i]);
    if (i < CI)            d_Bcat[i] = tb[i];
    else if (i < 2 * CI)   d_Bcat[i] = pb[i - CI];
    else if (i < 3 * CI)   d_Bcat[i] = gb[i - 2 * CI];
    if (i < CIN) { d_Sum[i] = 0.f; d_Sq[i] = 0.f; }
}

// ---------------- x [b][512][3136] fp32 -> xT16 [b][3136][512] fp16 (64x64 tiles) ----
__global__ void xT_k(const float* __restrict__ x)
{
    __shared__ __half t[64][66];
    const int tid = threadIdx.x;
    const int p0 = blockIdx.x * 64, c0 = blockIdx.y * 64, b = blockIdx.z;
    const float* xb = x + (size_t)b * CIN * NPIX;
    #pragma unroll
    for (int ps = 0; ps < 4; ps++) {
        int ch = (tid >> 4) + ps * 16;
        int px = (tid & 15) * 4;
        float4 v = *(const float4*)(xb + (size_t)(c0 + ch) * NPIX + p0 + px);
        t[ch][px + 0] = __float2half(v.x);
        t[ch][px + 1] = __float2half(v.y);
        t[ch][px + 2] = __float2half(v.z);
        t[ch][px + 3] = __float2half(v.w);
    }
    __syncthreads();
    __half* o = d_XT16 + (size_t)b * NPIX * CIN;
    #pragma unroll
    for (int ps = 0; ps < 2; ps++) {
        int px = (tid >> 3) + ps * 32;
        int cc = (tid & 7) * 8;
        __half v[8];
        #pragma unroll
        for (int i = 0; i < 8; i++) v[i] = t[cc + i][px];
        *(uint4*)(o + (size_t)(p0 + px) * CIN + c0 + cc) = *(uint4*)v;
    }
}

// ---------------- TPGT[:, :, 0:512] -> TP [b][512][pix] --------------------------
// 64x64 tiles, 16B global I/O both directions, conflict-free smem (stride 66).
__global__ void t2_k()
{
    __shared__ __half t[64][66];
    const int tid = threadIdx.x;
    const int p0 = blockIdx.x * 64, c0 = blockIdx.y * 64, b = blockIdx.z;
    const __half* src = d_TPGT + (size_t)b * NPIX * (3 * CI);
    // load: thread reads uint4 (8 ch) at pix p; stores as 4 u32 words.
    // bank = p + 4*(tid&7) + i  -> all 32 distinct per instruction.
    #pragma unroll
    for (int ps = 0; ps < 2; ps++) {
        int p = (tid >> 3) + ps * 32;
        int c = (tid & 7) * 8;
        uint4 v = *(const uint4*)(src + (size_t)(p0 + p) * (3 * CI) + c0 + c);
        uint32_t vv[4]; *(uint4*)vv = v;
        uint32_t* tw = (uint32_t*)&t[p][c];      // byte ofs p*132+2c ≡ 0 mod 4
        #pragma unroll
        for (int i = 0; i < 4; i++) tw[i] = vv[i];
    }
    __syncthreads();
    // gather: thread owns ch-pair (cA,cB) and an 8-pix block; reads u32 words.
    // bank = (px+i) + c2 -> all 32 distinct per instruction (conflict-free).
    const int w = tid >> 5, lane = tid & 31;
    const int c2  = (lane >> 2) + (w & 3) * 8;   // 0..31 pair index
    const int pxb = (lane & 3) + (w >> 2) * 4;   // 0..7
    const int px = pxb * 8;
    const int cA = 2 * c2, cB = cA + 1;
    __half vA[8], vB[8];
    #pragma unroll
    for (int i = 0; i < 8; i++) {
        uint32_t wv = *(const uint32_t*)&t[px + i][cA];
        vA[i] = __ushort_as_half((unsigned short)(wv & 0xFFFFu));
        vB[i] = __ushort_as_half((unsigned short)(wv >> 16));
    }
    __half* o = d_TP + (size_t)b * CIN * NPIX;
    *(uint4*)(o + (size_t)(c0 + cA) * NPIX + p0 + px) = *(uint4*)vA;
    *(uint4*)(o + (size_t)(c0 + cB) * NPIX + p0 + px) = *(uint4*)vB;
}

// ================= fp16 mma.sync GEMM, 4-stage cp.async pipeline =================
// D[M, N] = alpha * A @ B^T ; A: [M,K] fp16 K-contig, B: [N,K] fp16 K-contig.
// OMODE 0: C fp16 [M][ldc], optional per-col bias.
// OMODE 1: C fp32 [M][ldc] + per-row bias + residual + per-row BN stats (G4).
// OMODE 2: split-K fp32 partials into d_GP (G2); SPLIT chunks over K.
template<int OMODE, bool COL_BIAS, int SPLIT>
__global__ void __launch_bounds__(256, 2) gemm16(
    int Mtot, int Ntot, int KT, float alpha,
    const __half* __restrict__ A, int lda, long long sA,
    const __half* __restrict__ B, int ldb, long long sB,
    void* __restrict__ Cv, int ldc, long long sC,
    const float* __restrict__ bias,
    const float* __restrict__ res, long long sR)
{
    constexpr int STG32 = 2 * 128 * 20;              // 5120 u32 per stage (A+B)
    extern __shared__ uint32_t sm[];
    const uint32_t smb = smem_u32(sm);

    const int tid = threadIdx.x;
    int b = blockIdx.z, kt0 = 0, ktn = KT;
    float* partC = nullptr;
    if (SPLIT > 1) {
        b = blockIdx.z / SPLIT;
        int sp = blockIdx.z % SPLIT;
        int base = KT / SPLIT, rem = KT % SPLIT;
        kt0 = sp * base + (sp < rem ? sp : rem);
        ktn = base + (sp < rem ? 1 : 0);
        partC = d_GP + ((size_t)sp * B_ + b) * (CI * CI);
    }
    A += (long long)b * sA;
    B += (long long)b * sB;
    const int rowA = blockIdx.y * 128;
    const int colB = blockIdx.x * 128;
    const int warp = tid >> 5, lane = tid & 31;
    const int wr = warp >> 2, wc = warp & 3;         // 2x4 warp grid, 64x32 tiles
    const int g = lane >> 2, q = lane & 3;

    float acc[4][4][4];
    #pragma unroll
    for (int i = 0; i < 4; i++)
        #pragma unroll
        for (int j = 0; j < 4; j++)
            #pragma unroll
            for (int k = 0; k < 4; k++) acc[i][j][k] = 0.f;

    auto load_tile = [&](int s, int kt) {
        const uint32_t baseA = smb + (uint32_t)(s * STG32) * 4;
        #pragma unroll
        for (int j = 0; j < 2; j++) {                // A: 512 16B chunks
            int u = tid + j * 256;
            int row = u >> 2, c = u & 3;
            bool ok = rowA + row < Mtot;
            cp16(baseA + (uint32_t)(row * 20 + c * 4) * 4,
                 A + (size_t)(ok ? rowA + row : 0) * lda + kt * 32 + c * 8, ok);
        }
        const uint32_t baseB = baseA + 2560 * 4;
        #pragma unroll
        for (int j = 0; j < 2; j++) {                // B: 512 16B chunks
            int u = tid + j * 256;
            int row = u >> 2, c = u & 3;
            bool ok = colB + row < Ntot;
            cp16(baseB + (uint32_t)(row * 20 + c * 4) * 4,
                 B + (size_t)(ok ? colB + row : 0) * ldb + kt * 32 + c * 8, ok);
        }
        cp_commit();
    };

    auto compute = [&](int s) {
        const uint32_t* As_ = sm + s * STG32;
        const uint32_t* Bs_ = As_ + 2560;
        #pragma unroll
        for (int k16 = 0; k16 < 2; k16++) {
            const int ko = k16 * 8;
            uint32_t af[4][4], bf[4][2];
            #pragma unroll
            for (int mt = 0; mt < 4; mt++) {
                int m0 = wr * 64 + mt * 16 + g;
                af[mt][0] = As_[m0 * 20 + q + ko];
                af[mt][1] = As_[(m0 + 8) * 20 + q + ko];
                af[mt][2] = As_[m0 * 20 + q + 4 + ko];
                af[mt][3] = As_[(m0 + 8) * 20 + q + 4 + ko];
            }
            #pragma unroll
            for (int nt = 0; nt < 4; nt++) {
                int n0 = wc * 32 + nt * 8 + g;
                bf[nt][0] = Bs_[n0 * 20 + q + ko];
                bf[nt][1] = Bs_[n0 * 20 + q + 4 + ko];
            }
            #pragma unroll
            for (int mt = 0; mt < 4; mt++)
                #pragma unroll
                for (int nt = 0; nt < 4; nt++)
                    mma16(acc[mt][nt], af[mt], bf[nt]);
        }
    };

    // prologue: local tiles 0,1,2  (all our KT chunks are >= 3)
    load_tile(0, kt0);
    load_tile(1, kt0 + 1);
    load_tile(2, kt0 + 2);

    for (int lt = 0; lt < ktn; lt++) {
        cp_wait2();                                  // local tile lt resident
        __syncthreads();
        int nt = lt + 3;
        if (nt < ktn) load_tile(nt & 3, kt0 + nt);
        else cp_commit();                            // keep group count uniform
        compute(lt & 3);
    }

    // ---------------- epilogue ----------------
    if (OMODE == 0) {
        __half* C = ((__half*)Cv) + (long long)b * sC;
        #pragma unroll
        for (int mt = 0; mt < 4; mt++) {
            const int r0 = rowA + wr * 64 + mt * 16 + g;
            const int r1 = r0 + 8;
            #pragma unroll
            for (int nt = 0; nt < 4; nt++) {
                const int col = colB + wc * 32 + nt * 8 + 2 * q;
                if (col >= Ntot) continue;
                float v0 = acc[mt][nt][0] * alpha;
                float v1 = acc[mt][nt][1] * alpha;
                float v2 = acc[mt][nt][2] * alpha;
                float v3 = acc[mt][nt][3] * alpha;
                if (COL_BIAS) {
                    float b0 = bias[col], b1 = bias[col + 1];
                    v0 += b0; v1 += b1; v2 += b0; v3 += b1;
                }
                if (r0 < Mtot) *(__half2*)(C + (size_t)r0 * ldc + col) = __floats2half2_rn(v0, v1);
                if (r1 < Mtot) *(__half2*)(C + (size_t)r1 * ldc + col) = __floats2half2_rn(v2, v3);
            }
        }
    } else if (OMODE == 2) {
        // split-K fp32 partial store
        float* C = partC;
        #pragma unroll
        for (int mt = 0; mt < 4; mt++) {
            const int r0 = rowA + wr * 64 + mt * 16 + g;
            const int r1 = r0 + 8;
            #pragma unroll
            for (int nt = 0; nt < 4; nt++) {
                const int col = colB + wc * 32 + nt * 8 + 2 * q;
                if (col < Ntot) {
                    if (r0 < Mtot)
                        *(float2*)(C + (size_t)r0 * ldc + col) =
                            make_float2(acc[mt][nt][0] * alpha, acc[mt][nt][1] * alpha);
                    if (r1 < Mtot)
                        *(float2*)(C + (size_t)r1 * ldc + col) =
                            make_float2(acc[mt][nt][2] * alpha, acc[mt][nt][3] * alpha);
                }
            }
        }
    } else {
        // G4: row-major fp32 out + per-row bias + residual + per-row BN stats
        float* C = ((float*)Cv) + (long long)b * sC;
        const float* R = res + (long long)b * sR;
        float sumr[8], sqr[8];
        #pragma unroll
        for (int i = 0; i < 8; i++) { sumr[i] = 0.f; sqr[i] = 0.f; }

        #pragma unroll
        for (int mt = 0; mt < 4; mt++) {
            const int r0 = rowA + wr * 64 + mt * 16 + g;
            const int r1 = r0 + 8;
            const float bv0 = bias[r0];
            const float bv1 = bias[r1];
            float* c0p = C + (size_t)r0 * ldc;
            float* c1p = C + (size_t)r1 * ldc;
            const float* rr0 = R + (size_t)r0 * ldc;
            const float* rr1 = R + (size_t)r1 * ldc;
            #pragma unroll
            for (int nt = 0; nt < 4; nt++) {
                const int col = colB + wc * 32 + nt * 8 + 2 * q;
                if (col < Ntot) {
                    float2 e0 = *(const float2*)(rr0 + col);
                    float2 e1 = *(const float2*)(rr1 + col);
                    float v0 = acc[mt][nt][0] + bv0 + e0.x;
                    float v1 = acc[mt][nt][1] + bv0 + e0.y;
                    float v2 = acc[mt][nt][2] + bv1 + e1.x;
                    float v3 = acc[mt][nt][3] + bv1 + e1.y;
                    *(float2*)(c0p + col) = make_float2(v0, v1);
                    *(float2*)(c1p + col) = make_float2(v2, v3);
                    sumr[2 * mt]     += v0 + v1;
                    sqr [2 * mt]     += v0 * v0 + v1 * v1;
                    sumr[2 * mt + 1] += v2 + v3;
                    sqr [2 * mt + 1] += v2 * v2 + v3 * v3;
                }
            }
        }
        __syncthreads();
        float* sred = (float*)sm;
        if (tid < 128) { sred[tid] = 0.f; sred[128 + tid] = 0.f; }
        __syncthreads();
        #pragma unroll
        for (int i = 0; i < 8; i++) {
            int lr = wr * 64 + (i >> 1) * 16 + g + (i & 1) * 8;
            atomicAdd(&sred[lr], sumr[i]);
            atomicAdd(&sred[128 + lr], sqr[i]);
        }
        __syncthreads();
        if (tid < 128) {
            atomicAdd(&d_Sum[rowA + tid], sred[tid]);
            atomicAdd(&d_Sq [rowA + tid], sred[128 + tid]);
        }
    }
}

// ---------------- reduce G2 partials -> d_F16 ----------------
__global__ void reduce_f_k()
{
    const size_t per = (size_t)B_ * CI * CI;
    size_t gid = (size_t)blockIdx.x * 256 + threadIdx.x;
    size_t i4 = gid * 4;                       // element index (4 per thread)
    if (i4 >= per) return;
    float4 s0 = *(const float4*)(d_GP + 0 * per + i4);
    float4 s1 = *(const float4*)(d_GP + 1 * per + i4);
    float4 s2 = *(const float4*)(d_GP + 2 * per + i4);
    float4 s3 = *(const float4*)(d_GP + 3 * per + i4);
    float r0 = s0.x + s1.x + s2.x + s3.x;
    float r1 = s0.y + s1.y + s2.y + s3.y;
    float r2 = s0.z + s1.z + s2.z + s3.z;
    float r3 = s0.w + s1.w + s2.w + s3.w;
    __half2 h0 = __floats2half2_rn(r0, r1);
    __half2 h1 = __floats2half2_rn(r2, r3);
    *(__half2*)(d_F16 + i4)     = h0;
    *(__half2*)(d_F16 + i4 + 2) = h1;
}

// ---------------- BN finalize / apply ----------------
__global__ void finalize_k(const float* __restrict__ gamma, const float* __restrict__ beta)
{
    int c = threadIdx.x;
    if (c < CIN) {
        const float cnt = (float)((long long)B_ * NPIX);
        float mean = d_Sum[c] / cnt;
        float var  = d_Sq[c] / cnt - mean * mean;
        float s = gamma[c] * rsqrtf(var + EPSV);
        d_Scale[c] = s;
        d_Shift[c] = beta[c] - mean * s;
    }
}

__global__ void apply_k(float* __restrict__ out)
{
    const long long n4 = (long long)B_ * CIN * NPIX / 4;
    const long long stride = (long long)gridDim.x * blockDim.x;
    for (long long i = (long long)blockIdx.x * blockDim.x + threadIdx.x; i < n4; i += stride) {
        int c = (int)((i / (NPIX / 4)) % CIN);
        float s = d_Scale[c], sh = d_Shift[c];
        float4 v = ((float4*)out)[i];
        v.x = v.x * s + sh; v.y = v.y * s + sh;
        v.z = v.z * s + sh; v.w = v.w * s + sh;
        ((float4*)out)[i] = v;
    }
}

// ---------------- launch ----------------
extern "C" void kernel_launch(void* const* d_in, const int* in_sizes, int n_in,
                              void* d_out, int out_size)
{
    const float* x       = (const float*)d_in[0];
    const float* g_w     = (const float*)d_in[1];
    const float* g_b     = (const float*)d_in[2];
    const float* theta_w = (const float*)d_in[3];
    const float* theta_b = (const float*)d_in[4];
    const float* phi_w   = (const float*)d_in[5];
    const float* phi_b   = (const float*)d_in[6];
    const float* W_w     = (const float*)d_in[7];
    const float* W_b     = (const float*)d_in[8];
    const float* gamma   = (const float*)d_in[9];
    const float* beta    = (const float*)d_in[10];
    float* out = (float*)d_out;

    __half *xt, *tpgt, *tp, *f16, *yt, *wc16, *wr16;
    float *bcat;
    cudaGetSymbolAddress((void**)&xt,   d_XT16);
    cudaGetSymbolAddress((void**)&tpgt, d_TPGT);
    cudaGetSymbolAddress((void**)&tp,   d_TP);
    cudaGetSymbolAddress((void**)&f16,  d_F16);
    cudaGetSymbolAddress((void**)&yt,   d_YT);
    cudaGetSymbolAddress((void**)&wc16, d_Wcat16);
    cudaGetSymbolAddress((void**)&wr16, d_Wr16);
    cudaGetSymbolAddress((void**)&bcat, d_Bcat);

    constexpr int SMEM = 4 * 5120 * 4;               // 81920 B
    cudaFuncSetAttribute(gemm16<0, true,  1>, cudaFuncAttributeMaxDynamicSharedMemorySize, SMEM);
    cudaFuncSetAttribute(gemm16<2, false, 4>, cudaFuncAttributeMaxDynamicSharedMemorySize, SMEM);
    cudaFuncSetAttribute(gemm16<0, false, 1>, cudaFuncAttributeMaxDynamicSharedMemorySize, SMEM);
    cudaFuncSetAttribute(gemm16<1, false, 1>, cudaFuncAttributeMaxDynamicSharedMemorySize, SMEM);

    const long long sX   = (long long)CIN * NPIX;       // x / out per batch
    const long long sXT  = (long long)NPIX * CIN;
    const long long sTPG = (long long)NPIX * 3 * CI;
    const long long sTP  = (long long)CIN * NPIX;
    const long long sF   = (long long)CI * CI;
    const long long sYT  = (long long)NPIX * CI;

    // 0) prep weights + x transpose (49x64 = 3136 exact)
    prep_w<<<1536, 256>>>(g_w, g_b, theta_w, theta_b, phi_w, phi_b, W_w);
    xT_k<<<dim3(49, 8, B_), 256>>>(x);

    // 1) TPGT[pix][768] = xT16[pix][512k] @ Wcat16[768][512k]^T + Bcat[col]
    gemm16<0, true, 1><<<dim3(6, 25, B_), 256, SMEM>>>(
        NPIX, 3 * CI, CIN / 32, 1.f,
        xt, CIN, sXT,
        wc16, CIN, 0,
        tpgt, 3 * CI, sTPG,
        bcat, nullptr, 0);

    // 1b) transpose theta|phi cols -> TP [512][pix]
    t2_k<<<dim3(49, 8, B_), 256>>>();

    // 2) split-K gram: partials[sp][b] = theta @ phi^T / N over K chunk sp
    gemm16<2, false, 4><<<dim3(2, 2, B_ * 4), 256, SMEM>>>(
        CI, CI, NPIX / 32, 1.f / (float)NPIX,
        tp, NPIX, sTP,
        tp + (long long)CI * NPIX, NPIX, sTP,
        nullptr, CI, sF,
        nullptr, nullptr, 0);

    // 2b) reduce partials -> f16
    reduce_f_k<<<(B_ * CI * CI / 4 + 255) / 256, 256>>>();

    // 3) yT[pix][c] = gT[pix][256k] @ f[c][256k]^T   (gT = TPGT cols 512..767)
    gemm16<0, false, 1><<<dim3(2, 25, B_), 256, SMEM>>>(
        NPIX, CI, CI / 32, 1.f,
        tpgt + 2 * CI, 3 * CI, sTPG,
        f16, CI, sF,
        yt, CI, sYT,
        nullptr, nullptr, 0);

    // 4) z[ch][pix] = Wr16[512ch][256k] @ yT[pix][256k]^T + W_b[ch] + x  (row stats)
    gemm16<1, false, 1><<<dim3(25, 4, B_), 256, SMEM>>>(
        CIN, NPIX, CI / 32, 1.f,
        wr16, CI, 0,
        yt, CI, sYT,
        out, NPIX, sX,
        W_b, x, sX);

    // 5) BN finalize + apply
    finalize_k<<<1, 512>>>(gamma, beta);
    apply_k<<<2368, 256>>>(out);
}

// round 15
// speedup vs baseline: 1.3533x; 1.0476x over previous
#include <cuda_runtime.h>
#include <cuda_fp16.h>
#include <cstdint>

#define B_    32
#define CIN   512
#define CI    256
#define NPIX  3136
#define EPSV  1e-5f

// ---------------- scratch (static device globals; no allocation) ----------------
__device__ __align__(128) __half d_XT16[(size_t)B_ * NPIX * CIN];   // [b][pix][512]  x^T fp16
__device__ __align__(128) __half d_GT  [(size_t)B_ * NPIX * CI];    // [b][pix][256]  g^T
__device__ __align__(128) __half d_TP  [(size_t)B_ * CIN * NPIX];   // [b][512][pix]  theta|phi (pix-contig)
__device__ __align__(128) __half d_F16 [(size_t)B_ * CI * CI];      // [b][256][256]
__device__ __align__(128) __half d_YT  [(size_t)B_ * NPIX * CI];    // [b][pix][256]  y^T
__device__ __align__(128) __half d_Wcat16[3 * CI * CIN];            // [768][512]
__device__ __align__(128) __half d_Wr16[CIN * CI];                  // [512][256]
__device__ __align__(128) float d_GP[(size_t)4 * B_ * CI * CI];     // G2 split-K partials
__device__ float d_Bcat[3 * CI];
__device__ float d_Sum[CIN];
__device__ float d_Sq [CIN];
__device__ float d_Scale[CIN];
__device__ float d_Shift[CIN];

// ================= PTX helpers (sm_75/80+-portable) =================
__device__ __forceinline__ uint32_t smem_u32(const void* p) {
    uint32_t a;
    asm("{ .reg .u64 t; cvta.to.shared.u64 t, %1; cvt.u32.u64 %0, t; }" : "=r"(a) : "l"(p));
    return a;
}
__device__ __forceinline__ void cp16(uint32_t d, const void* s, bool ok) {
    int sz = ok ? 16 : 0;
    asm volatile("cp.async.cg.shared.global [%0], [%1], 16, %2;" :: "r"(d), "l"(s), "r"(sz) : "memory");
}
__device__ __forceinline__ void cp_commit() { asm volatile("cp.async.commit_group;" ::: "memory"); }
__device__ __forceinline__ void cp_wait2()  { asm volatile("cp.async.wait_group 2;" ::: "memory"); }
__device__ __forceinline__ void ldm4(uint32_t* r, uint32_t a) {
    asm volatile("ldmatrix.sync.aligned.m8n8.x4.shared.b16 {%0,%1,%2,%3}, [%4];"
        : "=r"(r[0]), "=r"(r[1]), "=r"(r[2]), "=r"(r[3]) : "r"(a));
}
__device__ __forceinline__ void ldm2(uint32_t* r, uint32_t a) {
    asm volatile("ldmatrix.sync.aligned.m8n8.x2.shared.b16 {%0,%1}, [%2];"
        : "=r"(r[0]), "=r"(r[1]) : "r"(a));
}
__device__ __forceinline__ void mma16(float* c, const uint32_t* a, const uint32_t* b) {
    asm volatile(
        "mma.sync.aligned.m16n8k16.row.col.f32.f16.f16.f32 "
        "{%0,%1,%2,%3}, {%4,%5,%6,%7}, {%8,%9}, {%0,%1,%2,%3};"
        : "+f"(c[0]), "+f"(c[1]), "+f"(c[2]), "+f"(c[3])
        : "r"(a[0]), "r"(a[1]), "r"(a[2]), "r"(a[3]), "r"(b[0]), "r"(b[1]));
}

// ---------------- prep: weights -> fp16, bias concat, zero stats ----------------
__global__ void prep_w(const float* __restrict__ gw, const float* __restrict__ gb,
                       const float* __restrict__ tw, const float* __restrict__ tb,
                       const float* __restrict__ pw, const float* __restrict__ pb,
                       const float* __restrict__ ww)
{
    int i = blockIdx.x * 256 + threadIdx.x;
    const int per = CI * CIN;
    if (i < 3 * per) {
        int m = i / per, off = i - m * per;
        d_Wcat16[i] = __float2half((m == 0 ? tw : (m == 1 ? pw : gw))[off]);
    }
    if (i < CIN * CI) d_Wr16[i] = __float2half(ww[i]);
    if (i < CI)            d_Bcat[i] = tb[i];
    else if (i < 2 * CI)   d_Bcat[i] = pb[i - CI];
    else if (i < 3 * CI)   d_Bcat[i] = gb[i - 2 * CI];
    if (i < CIN) { d_Sum[i] = 0.f; d_Sq[i] = 0.f; }
}

// ---------------- x [b][512][3136] fp32 -> xT16 [b][3136][512] fp16 (64x64 tiles) ----
__global__ void xT_k(const float* __restrict__ x)
{
    __shared__ __half t[64][66];
    const int tid = threadIdx.x;
    const int p0 = blockIdx.x * 64, c0 = blockIdx.y * 64, b = blockIdx.z;
    const float* xb = x + (size_t)b * CIN * NPIX;
    #pragma unroll
    for (int ps = 0; ps < 4; ps++) {
        int ch = (tid >> 4) + ps * 16;
        int px = (tid & 15) * 4;
        float4 v = *(const float4*)(xb + (size_t)(c0 + ch) * NPIX + p0 + px);
        t[ch][px + 0] = __float2half(v.x);
        t[ch][px + 1] = __float2half(v.y);
        t[ch][px + 2] = __float2half(v.z);
        t[ch][px + 3] = __float2half(v.w);
    }
    __syncthreads();
    __half* o = d_XT16 + (size_t)b * NPIX * CIN;
    #pragma unroll
    for (int ps = 0; ps < 2; ps++) {
        int px = (tid >> 3) + ps * 32;
        int cc = (tid & 7) * 8;
        __half v[8];
        #pragma unroll
        for (int i = 0; i < 8; i++) v[i] = t[cc + i][px];
        *(uint4*)(o + (size_t)(p0 + px) * CIN + c0 + cc) = *(uint4*)v;
    }
}

// ================= fp16 mma.sync GEMM, 4-stage cp.async + ldmatrix =================
// D[M, N] = alpha * A @ B^T ; A: [M,K] fp16 K-contig, B: [N,K] fp16 K-contig.
// OMODE 0: C fp16 [M][ldc] plain.
// OMODE 1: C fp32 [M][ldc] + per-row bias + residual + per-row BN stats (G4).
// OMODE 2: split-K fp32 partials into d_GP (G2).
// OMODE 3: G1 — rows=pix, cols=ch'[0..768): ch'<512 -> d_TP transposed; else d_GT.
// Block 128x128, 256 thr (8 warps, 2x4 grid of 64x32 tiles), KTILE=32 (2 k16 steps).
template<int OMODE, int SPLIT>
__global__ void __launch_bounds__(256, 2) gemm16(
    int Mtot, int Ntot, int KT, float alpha,
    const __half* __restrict__ A, int lda, long long sA,
    const __half* __restrict__ B, int ldb, long long sB,
    void* __restrict__ Cv, int ldc, long long sC,
    const float* __restrict__ bias,
    const float* __restrict__ res, long long sR)
{
    constexpr int STG32 = 2 * 128 * 20;              // 5120 u32 per stage (A+B)
    extern __shared__ uint32_t sm[];
    const uint32_t smb = smem_u32(sm);

    const int tid = threadIdx.x;
    int b = blockIdx.z, kt0 = 0, ktn = KT;
    float* partC = nullptr;
    if (SPLIT > 1) {
        b = blockIdx.z / SPLIT;
        int sp = blockIdx.z % SPLIT;
        int base = KT / SPLIT, rem = KT % SPLIT;
        kt0 = sp * base + (sp < rem ? sp : rem);
        ktn = base + (sp < rem ? 1 : 0);
        partC = d_GP + ((size_t)sp * B_ + b) * (CI * CI);
    }
    A += (long long)b * sA;
    B += (long long)b * sB;
    const int rowA = blockIdx.y * 128;
    const int colB = blockIdx.x * 128;
    const int warp = tid >> 5, lane = tid & 31;
    const int wr = warp >> 2, wc = warp & 3;         // 2x4 warp grid, 64x32 tiles
    const int g = lane >> 2, q = lane & 3;

    // ldmatrix per-thread address components (u32-word units within a stage)
    const int arow = wr * 64 + (lane & 7) + ((lane >> 3) & 1) * 8;  // + mt*16
    const int ah4  = ((lane >> 4) & 1) * 4;
    const int l15  = lane & 15;
    const int brow = wc * 32 + (l15 & 7);                            // + nt*8
    const int bh4  = (l15 >> 3) * 4;

    float acc[4][4][4];
    #pragma unroll
    for (int i = 0; i < 4; i++)
        #pragma unroll
        for (int j = 0; j < 4; j++)
            #pragma unroll
            for (int k = 0; k < 4; k++) acc[i][j][k] = 0.f;

    auto load_tile = [&](int s, int kt) {
        const uint32_t baseA = smb + (uint32_t)(s * STG32) * 4;
        #pragma unroll
        for (int j = 0; j < 2; j++) {                // A: 512 16B chunks
            int u = tid + j * 256;
            int row = u >> 2, c = u & 3;
            bool ok = rowA + row < Mtot;
            cp16(baseA + (uint32_t)(row * 20 + c * 4) * 4,
                 A + (size_t)(ok ? rowA + row : 0) * lda + kt * 32 + c * 8, ok);
        }
        const uint32_t baseB = baseA + 2560 * 4;
        #pragma unroll
        for (int j = 0; j < 2; j++) {                // B: 512 16B chunks
            int u = tid + j * 256;
            int row = u >> 2, c = u & 3;
            bool ok = colB + row < Ntot;
            cp16(baseB + (uint32_t)(row * 20 + c * 4) * 4,
                 B + (size_t)(ok ? colB + row : 0) * ldb + kt * 32 + c * 8, ok);
        }
        cp_commit();
    };

    auto compute = [&](int s) {
        const uint32_t stage = smb + (uint32_t)(s * STG32) * 4;
        const uint32_t aBase = stage + (uint32_t)(arow * 20 + ah4) * 4;
        const uint32_t bBase = stage + 2560 * 4 + (uint32_t)(brow * 20 + bh4) * 4;
        #pragma unroll
        for (int k16 = 0; k16 < 2; k16++) {
            uint32_t af[4][4], bf[4][2];
            #pragma unroll
            for (int mt = 0; mt < 4; mt++)
                ldm4(af[mt], aBase + (uint32_t)(mt * 1280 + k16 * 32));
            #pragma unroll
            for (int nt = 0; nt < 4; nt++)
                ldm2(bf[nt], bBase + (uint32_t)(nt * 640 + k16 * 32));
            #pragma unroll
            for (int mt = 0; mt < 4; mt++)
                #pragma unroll
                for (int nt = 0; nt < 4; nt++)
                    mma16(acc[mt][nt], af[mt], bf[nt]);
        }
    };

    // prologue: local tiles 0,1,2  (all KT chunks are >= 3)
    load_tile(0, kt0);
    load_tile(1, kt0 + 1);
    load_tile(2, kt0 + 2);

    for (int lt = 0; lt < ktn; lt++) {
        cp_wait2();                                  // local tile lt resident
        __syncthreads();
        int nt = lt + 3;
        if (nt < ktn) load_tile(nt & 3, kt0 + nt);
        else cp_commit();                            // keep group count uniform
        compute(lt & 3);
    }

    // ---------------- epilogue ----------------
    if (OMODE == 0) {
        __half* C = ((__half*)Cv) + (long long)b * sC;
        #pragma unroll
        for (int mt = 0; mt < 4; mt++) {
            const int r0 = rowA + wr * 64 + mt * 16 + g;
            const int r1 = r0 + 8;
            #pragma unroll
            for (int nt = 0; nt < 4; nt++) {
                const int col = colB + wc * 32 + nt * 8 + 2 * q;
                if (col >= Ntot) continue;
                float v0 = acc[mt][nt][0] * alpha;
                float v1 = acc[mt][nt][1] * alpha;
                float v2 = acc[mt][nt][2] * alpha;
                float v3 = acc[mt][nt][3] * alpha;
                if (r0 < Mtot) *(__half2*)(C + (size_t)r0 * ldc + col) = __floats2half2_rn(v0, v1);
                if (r1 < Mtot) *(__half2*)(C + (size_t)r1 * ldc + col) = __floats2half2_rn(v2, v3);
            }
        }
    } else if (OMODE == 3) {
        // G1: rows = pix, cols = ch' in [0,768). Block-uniform split at 512.
        __half* TPb = d_TP + (size_t)b * ((size_t)CIN * NPIX);
        __half* GTb = d_GT + (size_t)b * ((size_t)NPIX * CI);
        #pragma unroll
        for (int mt = 0; mt < 4; mt++) {
            const int r0 = rowA + wr * 64 + mt * 16 + g;
            const int r1 = r0 + 8;
            #pragma unroll
            for (int nt = 0; nt < 4; nt++) {
                const int col = colB + wc * 32 + nt * 8 + 2 * q;
                float v0 = acc[mt][nt][0] + bias[col];
                float v1 = acc[mt][nt][1] + bias[col + 1];
                float v2 = acc[mt][nt][2] + bias[col];
                float v3 = acc[mt][nt][3] + bias[col + 1];
                if (colB < 512) {                    // theta|phi -> TP[ch][pix]
                    if (r0 < Mtot) {
                        TPb[(size_t)col * NPIX + r0]       = __float2half_rn(v0);
                        TPb[(size_t)(col + 1) * NPIX + r0] = __float2half_rn(v1);
                    }
                    if (r1 < Mtot) {
                        TPb[(size_t)col * NPIX + r1]       = __float2half_rn(v2);
                        TPb[(size_t)(col + 1) * NPIX + r1] = __float2half_rn(v3);
                    }
                } else {                             // g -> GT[pix][ch-512]
                    const int gc = col - 512;
                    if (r0 < Mtot) *(__half2*)(GTb + (size_t)r0 * CI + gc) = __floats2half2_rn(v0, v1);
                    if (r1 < Mtot) *(__half2*)(GTb + (size_t)r1 * CI + gc) = __floats2half2_rn(v2, v3);
                }
            }
        }
    } else if (OMODE == 2) {
        // split-K fp32 partial store
        float* C = partC;
        #pragma unroll
        for (int mt = 0; mt < 4; mt++) {
            const int r0 = rowA + wr * 64 + mt * 16 + g;
            const int r1 = r0 + 8;
            #pragma unroll
            for (int nt = 0; nt < 4; nt++) {
                const int col = colB + wc * 32 + nt * 8 + 2 * q;
                if (col < Ntot) {
                    if (r0 < Mtot)
                        *(float2*)(C + (size_t)r0 * ldc + col) =
                            make_float2(acc[mt][nt][0] * alpha, acc[mt][nt][1] * alpha);
                    if (r1 < Mtot)
                        *(float2*)(C + (size_t)r1 * ldc + col) =
                            make_float2(acc[mt][nt][2] * alpha, acc[mt][nt][3] * alpha);
                }
            }
        }
    } else {
        // G4: row-major fp32 out + per-row bias + residual + per-row BN stats
        float* C = ((float*)Cv) + (long long)b * sC;
        const float* R = res + (long long)b * sR;
        float sumr[8], sqr[8];
        #pragma unroll
        for (int i = 0; i < 8; i++) { sumr[i] = 0.f; sqr[i] = 0.f; }

        #pragma unroll
        for (int mt = 0; mt < 4; mt++) {
            const int r0 = rowA + wr * 64 + mt * 16 + g;
            const int r1 = r0 + 8;
            const float bv0 = bias[r0];
            const float bv1 = bias[r1];
            float* c0p = C + (size_t)r0 * ldc;
            float* c1p = C + (size_t)r1 * ldc;
            const float* rr0 = R + (size_t)r0 * ldc;
            const float* rr1 = R + (size_t)r1 * ldc;
            #pragma unroll
            for (int nt = 0; nt < 4; nt++) {
                const int col = colB + wc * 32 + nt * 8 + 2 * q;
                if (col < Ntot) {
                    float2 e0 = *(const float2*)(rr0 + col);
                    float2 e1 = *(const float2*)(rr1 + col);
                    float v0 = acc[mt][nt][0] + bv0 + e0.x;
                    float v1 = acc[mt][nt][1] + bv0 + e0.y;
                    float v2 = acc[mt][nt][2] + bv1 + e1.x;
                    float v3 = acc[mt][nt][3] + bv1 + e1.y;
                    *(float2*)(c0p + col) = make_float2(v0, v1);
                    *(float2*)(c1p + col) = make_float2(v2, v3);
                    sumr[2 * mt]     += v0 + v1;
                    sqr [2 * mt]     += v0 * v0 + v1 * v1;
                    sumr[2 * mt + 1] += v2 + v3;
                    sqr [2 * mt + 1] += v2 * v2 + v3 * v3;
                }
            }
        }
        __syncthreads();
        float* sred = (float*)sm;
        if (tid < 128) { sred[tid] = 0.f; sred[128 + tid] = 0.f; }
        __syncthreads();
        #pragma unroll
        for (int i = 0; i < 8; i++) {
            int lr = wr * 64 + (i >> 1) * 16 + g + (i & 1) * 8;
            atomicAdd(&sred[lr], sumr[i]);
            atomicAdd(&sred[128 + lr], sqr[i]);
        }
        __syncthreads();
        if (tid < 128) {
            atomicAdd(&d_Sum[rowA + tid], sred[tid]);
            atomicAdd(&d_Sq [rowA + tid], sred[128 + tid]);
        }
    }
}

// ---------------- reduce G2 partials -> d_F16 ----------------
__global__ void reduce_f_k()
{
    const size_t per = (size_t)B_ * CI * CI;
    size_t gid = (size_t)blockIdx.x * 256 + threadIdx.x;
    size_t i4 = gid * 4;
    if (i4 >= per) return;
    float4 s0 = *(const float4*)(d_GP + 0 * per + i4);
    float4 s1 = *(const float4*)(d_GP + 1 * per + i4);
    float4 s2 = *(const float4*)(d_GP + 2 * per + i4);
    float4 s3 = *(const float4*)(d_GP + 3 * per + i4);
    *(__half2*)(d_F16 + i4)     = __floats2half2_rn(s0.x + s1.x + s2.x + s3.x,
                                                    s0.y + s1.y + s2.y + s3.y);
    *(__half2*)(d_F16 + i4 + 2) = __floats2half2_rn(s0.z + s1.z + s2.z + s3.z,
                                                    s0.w + s1.w + s2.w + s3.w);
}

// ---------------- BN finalize / apply ----------------
__global__ void finalize_k(const float* __restrict__ gamma, const float* __restrict__ beta)
{
    int c = threadIdx.x;
    if (c < CIN) {
        const float cnt = (float)((long long)B_ * NPIX);
        float mean = d_Sum[c] / cnt;
        float var  = d_Sq[c] / cnt - mean * mean;
        float s = gamma[c] * rsqrtf(var + EPSV);
        d_Scale[c] = s;
        d_Shift[c] = beta[c] - mean * s;
    }
}

__global__ void apply_k(float* __restrict__ out)
{
    const long long n4 = (long long)B_ * CIN * NPIX / 4;
    const long long stride = (long long)gridDim.x * blockDim.x;
    for (long long i = (long long)blockIdx.x * blockDim.x + threadIdx.x; i < n4; i += stride) {
        int c = (int)((i / (NPIX / 4)) % CIN);
        float s = d_Scale[c], sh = d_Shift[c];
        float4 v = ((float4*)out)[i];
        v.x = v.x * s + sh; v.y = v.y * s + sh;
        v.z = v.z * s + sh; v.w = v.w * s + sh;
        ((float4*)out)[i] = v;
    }
}

// ---------------- launch ----------------
extern "C" void kernel_launch(void* const* d_in, const int* in_sizes, int n_in,
                              void* d_out, int out_size)
{
    const float* x       = (const float*)d_in[0];
    const float* g_w     = (const float*)d_in[1];
    const float* g_b     = (const float*)d_in[2];
    const float* theta_w = (const float*)d_in[3];
    const float* theta_b = (const float*)d_in[4];
    const float* phi_w   = (const float*)d_in[5];
    const float* phi_b   = (const float*)d_in[6];
    const float* W_w     = (const float*)d_in[7];
    const float* W_b     = (const float*)d_in[8];
    const float* gamma   = (const float*)d_in[9];
    const float* beta    = (const float*)d_in[10];
    float* out = (float*)d_out;

    __half *xt, *gt, *tp, *f16, *yt, *wc16, *wr16;
    float *bcat;
    cudaGetSymbolAddress((void**)&xt,   d_XT16);
    cudaGetSymbolAddress((void**)&gt,   d_GT);
    cudaGetSymbolAddress((void**)&tp,   d_TP);
    cudaGetSymbolAddress((void**)&f16,  d_F16);
    cudaGetSymbolAddress((void**)&yt,   d_YT);
    cudaGetSymbolAddress((void**)&wc16, d_Wcat16);
    cudaGetSymbolAddress((void**)&wr16, d_Wr16);
    cudaGetSymbolAddress((void**)&bcat, d_Bcat);

    constexpr int SMEM = 4 * 5120 * 4;               // 81920 B
    cudaFuncSetAttribute(gemm16<3, 1>, cudaFuncAttributeMaxDynamicSharedMemorySize, SMEM);
    cudaFuncSetAttribute(gemm16<2, 4>, cudaFuncAttributeMaxDynamicSharedMemorySize, SMEM);
    cudaFuncSetAttribute(gemm16<0, 1>, cudaFuncAttributeMaxDynamicSharedMemorySize, SMEM);
    cudaFuncSetAttribute(gemm16<1, 1>, cudaFuncAttributeMaxDynamicSharedMemorySize, SMEM);

    const long long sX   = (long long)CIN * NPIX;       // x / out per batch
    const long long sXT  = (long long)NPIX * CIN;
    const long long sGT  = (long long)NPIX * CI;
    const long long sTP  = (long long)CIN * NPIX;
    const long long sF   = (long long)CI * CI;
    const long long sYT  = (long long)NPIX * CI;

    // 0) prep weights + x transpose
    prep_w<<<1536, 256>>>(g_w, g_b, theta_w, theta_b, phi_w, phi_b, W_w);
    xT_k<<<dim3(49, 8, B_), 256>>>(x);

    // 1) G1: xT16 @ Wcat^T + Bcat -> theta|phi into TP[ch][pix], g into GT[pix][256]
    gemm16<3, 1><<<dim3(6, 25, B_), 256, SMEM>>>(
        NPIX, 3 * CI, CIN / 32, 1.f,
        xt, CIN, sXT,
        wc16, CIN, 0,
        nullptr, 0, 0,
        bcat, nullptr, 0);

    // 2) split-K gram: partials[sp][b] = theta @ phi^T / N over K chunk sp
    gemm16<2, 4><<<dim3(2, 2, B_ * 4), 256, SMEM>>>(
        CI, CI, NPIX / 32, 1.f / (float)NPIX,
        tp, NPIX, sTP,
        tp + (long long)CI * NPIX, NPIX, sTP,
        nullptr, CI, sF,
        nullptr, nullptr, 0);

    // 2b) reduce partials -> f16
    reduce_f_k<<<(B_ * CI * CI / 4 + 255) / 256, 256>>>();

    // 3) yT[pix][c] = GT[pix][256k] @ f[c][256k]^T
    gemm16<0, 1><<<dim3(2, 25, B_), 256, SMEM>>>(
        NPIX, CI, CI / 32, 1.f,
        gt, CI, sGT,
        f16, CI, sF,
        yt, CI, sYT,
        nullptr, nullptr, 0);

    // 4) z[ch][pix] = Wr16[512ch][256k] @ yT[pix][256k]^T + W_b[ch] + x  (row stats)
    gemm16<1, 1><<<dim3(25, 4, B_), 256, SMEM>>>(
        CIN, NPIX, CI / 32, 1.f,
        wr16, CI, 0,
        yt, CI, sYT,
        out, NPIX, sX,
        W_b, x, sX);

    // 5) BN finalize + apply
    finalize_k<<<1, 512>>>(gamma, beta);
    apply_k<<<2368, 256>>>(out);
}

// round 16
// speedup vs baseline: 1.3568x; 1.0026x over previous
#include <cuda_runtime.h>
#include <cuda_fp16.h>
#include <cstdint>

#define B_    32
#define CIN   512
#define CI    256
#define NPIX  3136
#define EPSV  1e-5f

// ---------------- scratch (static device globals; no allocation) ----------------
__device__ __align__(128) __half d_XT16[(size_t)B_ * NPIX * CIN];   // [b][pix][512]  x^T fp16
__device__ __align__(128) __half d_GT  [(size_t)B_ * NPIX * CI];    // [b][pix][256]  g^T
__device__ __align__(128) __half d_TP  [(size_t)B_ * CIN * NPIX];   // [b][512][pix]  theta|phi (pix-contig)
__device__ __align__(128) __half d_F16 [(size_t)B_ * CI * CI];      // [b][256][256]
__device__ __align__(128) __half d_YT  [(size_t)B_ * NPIX * CI];    // [b][pix][256]  y^T
__device__ __align__(128) __half d_Wcat16[3 * CI * CIN];            // [768][512]
__device__ __align__(128) __half d_Wr16[CIN * CI];                  // [512][256]
__device__ __align__(128) float d_GP[(size_t)2 * B_ * CI * CI];     // G2 split-K partials
__device__ float d_Bcat[3 * CI];
__device__ float d_Sum[CIN];
__device__ float d_Sq [CIN];
__device__ float d_Scale[CIN];
__device__ float d_Shift[CIN];

// ================= PTX helpers (sm_75/80+-portable) =================
__device__ __forceinline__ uint32_t smem_u32(const void* p) {
    uint32_t a;
    asm("{ .reg .u64 t; cvta.to.shared.u64 t, %1; cvt.u32.u64 %0, t; }" : "=r"(a) : "l"(p));
    return a;
}
__device__ __forceinline__ void cp16(uint32_t d, const void* s, bool ok) {
    int sz = ok ? 16 : 0;
    asm volatile("cp.async.cg.shared.global [%0], [%1], 16, %2;" :: "r"(d), "l"(s), "r"(sz) : "memory");
}
__device__ __forceinline__ void cp_commit() { asm volatile("cp.async.commit_group;" ::: "memory"); }
__device__ __forceinline__ void cp_wait2()  { asm volatile("cp.async.wait_group 2;" ::: "memory"); }
__device__ __forceinline__ void ldm4(uint32_t* r, uint32_t a) {
    asm volatile("ldmatrix.sync.aligned.m8n8.x4.shared.b16 {%0,%1,%2,%3}, [%4];"
        : "=r"(r[0]), "=r"(r[1]), "=r"(r[2]), "=r"(r[3]) : "r"(a));
}
__device__ __forceinline__ void ldm2(uint32_t* r, uint32_t a) {
    asm volatile("ldmatrix.sync.aligned.m8n8.x2.shared.b16 {%0,%1}, [%2];"
        : "=r"(r[0]), "=r"(r[1]) : "r"(a));
}
__device__ __forceinline__ void mma16(float* c, const uint32_t* a, const uint32_t* b) {
    asm volatile(
        "mma.sync.aligned.m16n8k16.row.col.f32.f16.f16.f32 "
        "{%0,%1,%2,%3}, {%4,%5,%6,%7}, {%8,%9}, {%0,%1,%2,%3};"
        : "+f"(c[0]), "+f"(c[1]), "+f"(c[2]), "+f"(c[3])
        : "r"(a[0]), "r"(a[1]), "r"(a[2]), "r"(a[3]), "r"(b[0]), "r"(b[1]));
}

// ---------------- prep: weights -> fp16, bias concat, zero stats ----------------
__global__ void prep_w(const float* __restrict__ gw, const float* __restrict__ gb,
                       const float* __restrict__ tw, const float* __restrict__ tb,
                       const float* __restrict__ pw, const float* __restrict__ pb,
                       const float* __restrict__ ww)
{
    int i = blockIdx.x * 256 + threadIdx.x;
    const int per = CI * CIN;
    if (i < 3 * per) {
        int m = i / per, off = i - m * per;
        d_Wcat16[i] = __float2half((m == 0 ? tw : (m == 1 ? pw : gw))[off]);
    }
    if (i < CIN * CI) d_Wr16[i] = __float2half(ww[i]);
    if (i < CI)            d_Bcat[i] = tb[i];
    else if (i < 2 * CI)   d_Bcat[i] = pb[i - CI];
    else if (i < 3 * CI)   d_Bcat[i] = gb[i - 2 * CI];
    if (i < CIN) { d_Sum[i] = 0.f; d_Sq[i] = 0.f; }
}

// ---------------- x [b][512][3136] fp32 -> xT16 [b][3136][512] fp16 (64x64 tiles) ----
__global__ void xT_k(const float* __restrict__ x)
{
    __shared__ __half t[64][66];
    const int tid = threadIdx.x;
    const int p0 = blockIdx.x * 64, c0 = blockIdx.y * 64, b = blockIdx.z;
    const float* xb = x + (size_t)b * CIN * NPIX;
    #pragma unroll
    for (int ps = 0; ps < 4; ps++) {
        int ch = (tid >> 4) + ps * 16;
        int px = (tid & 15) * 4;
        float4 v = *(const float4*)(xb + (size_t)(c0 + ch) * NPIX + p0 + px);
        t[ch][px + 0] = __float2half(v.x);
        t[ch][px + 1] = __float2half(v.y);
        t[ch][px + 2] = __float2half(v.z);
        t[ch][px + 3] = __float2half(v.w);
    }
    __syncthreads();
    __half* o = d_XT16 + (size_t)b * NPIX * CIN;
    #pragma unroll
    for (int ps = 0; ps < 2; ps++) {
        int px = (tid >> 3) + ps * 32;
        int cc = (tid & 7) * 8;
        __half v[8];
        #pragma unroll
        for (int i = 0; i < 8; i++) v[i] = t[cc + i][px];
        *(uint4*)(o + (size_t)(p0 + px) * CIN + c0 + cc) = *(uint4*)v;
    }
}

// ================= fp16 mma.sync GEMM, 4-stage cp.async + pipelined ldmatrix =====
// D[M, N] = alpha * A @ B^T ; A: [M,K] fp16 K-contig, B: [N,K] fp16 K-contig.
// OMODE 0: C fp16 [M][ldc] plain.
// OMODE 1: C fp32 [M][ldc] + per-row bias + residual + per-row BN stats (G4).
// OMODE 2: split-K fp32 partials into d_GP (G2).
// OMODE 3: G1 — rows=pix, cols=ch'[0..768): ch'<512 -> d_TP transposed; else d_GT.
// Block 128x128, 256 thr (8 warps, 2x4 grid of 64x32 tiles), KTILE=32 (2 k16 steps).
template<int OMODE, int SPLIT>
__global__ void __launch_bounds__(256, 2) gemm16(
    int Mtot, int Ntot, int KT, float alpha,
    const __half* __restrict__ A, int lda, long long sA,
    const __half* __restrict__ B, int ldb, long long sB,
    void* __restrict__ Cv, int ldc, long long sC,
    const float* __restrict__ bias,
    const float* __restrict__ res, long long sR)
{
    constexpr int STG32 = 2 * 128 * 20;              // 5120 u32 per stage (A+B)
    extern __shared__ uint32_t sm[];
    const uint32_t smb = smem_u32(sm);

    const int tid = threadIdx.x;
    int b = blockIdx.z, kt0 = 0, ktn = KT;
    float* partC = nullptr;
    if (SPLIT > 1) {
        b = blockIdx.z / SPLIT;
        int sp = blockIdx.z % SPLIT;
        int base = KT / SPLIT, rem = KT % SPLIT;
        kt0 = sp * base + (sp < rem ? sp : rem);
        ktn = base + (sp < rem ? 1 : 0);
        partC = d_GP + ((size_t)sp * B_ + b) * (CI * CI);
    }
    A += (long long)b * sA;
    B += (long long)b * sB;
    const int rowA = blockIdx.y * 128;
    const int colB = blockIdx.x * 128;
    const int warp = tid >> 5, lane = tid & 31;
    const int wr = warp >> 2, wc = warp & 3;         // 2x4 warp grid, 64x32 tiles
    const int g = lane >> 2, q = lane & 3;

    // ldmatrix per-thread address components (u32-word units within a stage)
    const int arow = wr * 64 + (lane & 7) + ((lane >> 3) & 1) * 8;  // + mt*16
    const int ah4  = ((lane >> 4) & 1) * 4;
    const int l15  = lane & 15;
    const int brow = wc * 32 + (l15 & 7);                            // + nt*8
    const int bh4  = (l15 >> 3) * 4;

    float acc[4][4][4];
    #pragma unroll
    for (int i = 0; i < 4; i++)
        #pragma unroll
        for (int j = 0; j < 4; j++)
            #pragma unroll
            for (int k = 0; k < 4; k++) acc[i][j][k] = 0.f;

    auto load_tile = [&](int s, int kt) {
        const uint32_t baseA = smb + (uint32_t)(s * STG32) * 4;
        #pragma unroll
        for (int j = 0; j < 2; j++) {                // A: 512 16B chunks
            int u = tid + j * 256;
            int row = u >> 2, c = u & 3;
            bool ok = rowA + row < Mtot;
            cp16(baseA + (uint32_t)(row * 20 + c * 4) * 4,
                 A + (size_t)(ok ? rowA + row : 0) * lda + kt * 32 + c * 8, ok);
        }
        const uint32_t baseB = baseA + 2560 * 4;
        #pragma unroll
        for (int j = 0; j < 2; j++) {                // B: 512 16B chunks
            int u = tid + j * 256;
            int row = u >> 2, c = u & 3;
            bool ok = colB + row < Ntot;
            cp16(baseB + (uint32_t)(row * 20 + c * 4) * 4,
                 B + (size_t)(ok ? colB + row : 0) * ldb + kt * 32 + c * 8, ok);
        }
        cp_commit();
    };

    // Software-pipelined fragment consumption: all B frags preloaded (both k16),
    // A frags stream through a rotating (cur,next) pair so every ldmatrix has
    // 4 MMAs between issue and first use. Live frag regs: 16(B) + 8(A).
    auto compute = [&](int s) {
        const uint32_t stage = smb + (uint32_t)(s * STG32) * 4;
        const uint32_t aBase = stage + (uint32_t)(arow * 20 + ah4) * 4;
        const uint32_t bBase = stage + 2560 * 4 + (uint32_t)(brow * 20 + bh4) * 4;
        uint32_t bf[2][4][2];
        #pragma unroll
        for (int k16 = 0; k16 < 2; k16++)
            #pragma unroll
            for (int nt = 0; nt < 4; nt++)
                ldm2(bf[k16][nt], bBase + (uint32_t)(nt * 640 + k16 * 32));
        #pragma unroll
        for (int k16 = 0; k16 < 2; k16++) {
            uint32_t afc[4], afn[4];
            ldm4(afc, aBase + (uint32_t)(k16 * 32));
            #pragma unroll
            for (int mt = 0; mt < 4; mt++) {
                if (mt < 3)
                    ldm4(afn, aBase + (uint32_t)((mt + 1) * 1280 + k16 * 32));
                #pragma unroll
                for (int nt = 0; nt < 4; nt++)
                    mma16(acc[mt][nt], afc, bf[k16][nt]);
                if (mt < 3) {
                    #pragma unroll
                    for (int i = 0; i < 4; i++) afc[i] = afn[i];
                }
            }
        }
    };

    // prologue: local tiles 0,1,2  (all KT chunks are >= 3)
    load_tile(0, kt0);
    load_tile(1, kt0 + 1);
    load_tile(2, kt0 + 2);

    for (int lt = 0; lt < ktn; lt++) {
        cp_wait2();                                  // local tile lt resident
        __syncthreads();
        int nt = lt + 3;
        if (nt < ktn) load_tile(nt & 3, kt0 + nt);
        else cp_commit();                            // keep group count uniform
        compute(lt & 3);
    }

    // ---------------- epilogue ----------------
    if (OMODE == 0) {
        __half* C = ((__half*)Cv) + (long long)b * sC;
        #pragma unroll
        for (int mt = 0; mt < 4; mt++) {
            const int r0 = rowA + wr * 64 + mt * 16 + g;
            const int r1 = r0 + 8;
            #pragma unroll
            for (int nt = 0; nt < 4; nt++) {
                const int col = colB + wc * 32 + nt * 8 + 2 * q;
                if (col >= Ntot) continue;
                float v0 = acc[mt][nt][0] * alpha;
                float v1 = acc[mt][nt][1] * alpha;
                float v2 = acc[mt][nt][2] * alpha;
                float v3 = acc[mt][nt][3] * alpha;
                if (r0 < Mtot) *(__half2*)(C + (size_t)r0 * ldc + col) = __floats2half2_rn(v0, v1);
                if (r1 < Mtot) *(__half2*)(C + (size_t)r1 * ldc + col) = __floats2half2_rn(v2, v3);
            }
        }
    } else if (OMODE == 3) {
        // G1: rows = pix, cols = ch' in [0,768). Block-uniform split at 512.
        __half* TPb = d_TP + (size_t)b * ((size_t)CIN * NPIX);
        __half* GTb = d_GT + (size_t)b * ((size_t)NPIX * CI);
        #pragma unroll
        for (int mt = 0; mt < 4; mt++) {
            const int r0 = rowA + wr * 64 + mt * 16 + g;
            const int r1 = r0 + 8;
            #pragma unroll
            for (int nt = 0; nt < 4; nt++) {
                const int col = colB + wc * 32 + nt * 8 + 2 * q;
                float v0 = acc[mt][nt][0] + bias[col];
                float v1 = acc[mt][nt][1] + bias[col + 1];
                float v2 = acc[mt][nt][2] + bias[col];
                float v3 = acc[mt][nt][3] + bias[col + 1];
                if (colB < 512) {                    // theta|phi -> TP[ch][pix]
                    if (r0 < Mtot) {
                        TPb[(size_t)col * NPIX + r0]       = __float2half_rn(v0);
                        TPb[(size_t)(col + 1) * NPIX + r0] = __float2half_rn(v1);
                    }
                    if (r1 < Mtot) {
                        TPb[(size_t)col * NPIX + r1]       = __float2half_rn(v2);
                        TPb[(size_t)(col + 1) * NPIX + r1] = __float2half_rn(v3);
                    }
                } else {                             // g -> GT[pix][ch-512]
                    const int gc = col - 512;
                    if (r0 < Mtot) *(__half2*)(GTb + (size_t)r0 * CI + gc) = __floats2half2_rn(v0, v1);
                    if (r1 < Mtot) *(__half2*)(GTb + (size_t)r1 * CI + gc) = __floats2half2_rn(v2, v3);
                }
            }
        }
    } else if (OMODE == 2) {
        // split-K fp32 partial store
        float* C = partC;
        #pragma unroll
        for (int mt = 0; mt < 4; mt++) {
            const int r0 = rowA + wr * 64 + mt * 16 + g;
            const int r1 = r0 + 8;
            #pragma unroll
            for (int nt = 0; nt < 4; nt++) {
                const int col = colB + wc * 32 + nt * 8 + 2 * q;
                if (col < Ntot) {
                    if (r0 < Mtot)
                        *(float2*)(C + (size_t)r0 * ldc + col) =
                            make_float2(acc[mt][nt][0] * alpha, acc[mt][nt][1] * alpha);
                    if (r1 < Mtot)
                        *(float2*)(C + (size_t)r1 * ldc + col) =
                            make_float2(acc[mt][nt][2] * alpha, acc[mt][nt][3] * alpha);
                }
            }
        }
    } else {
        // G4: row-major fp32 out + per-row bias + residual + per-row BN stats
        float* C = ((float*)Cv) + (long long)b * sC;
        const float* R = res + (long long)b * sR;
        float sumr[8], sqr[8];
        #pragma unroll
        for (int i = 0; i < 8; i++) { sumr[i] = 0.f; sqr[i] = 0.f; }

        #pragma unroll
        for (int mt = 0; mt < 4; mt++) {
            const int r0 = rowA + wr * 64 + mt * 16 + g;
            const int r1 = r0 + 8;
            const float bv0 = bias[r0];
            const float bv1 = bias[r1];
            float* c0p = C + (size_t)r0 * ldc;
            float* c1p = C + (size_t)r1 * ldc;
            const float* rr0 = R + (size_t)r0 * ldc;
            const float* rr1 = R + (size_t)r1 * ldc;
            #pragma unroll
            for (int nt = 0; nt < 4; nt++) {
                const int col = colB + wc * 32 + nt * 8 + 2 * q;
                if (col < Ntot) {
                    float2 e0 = *(const float2*)(rr0 + col);
                    float2 e1 = *(const float2*)(rr1 + col);
                    float v0 = acc[mt][nt][0] + bv0 + e0.x;
                    float v1 = acc[mt][nt][1] + bv0 + e0.y;
                    float v2 = acc[mt][nt][2] + bv1 + e1.x;
                    float v3 = acc[mt][nt][3] + bv1 + e1.y;
                    *(float2*)(c0p + col) = make_float2(v0, v1);
                    *(float2*)(c1p + col) = make_float2(v2, v3);
                    sumr[2 * mt]     += v0 + v1;
                    sqr [2 * mt]     += v0 * v0 + v1 * v1;
                    sumr[2 * mt + 1] += v2 + v3;
                    sqr [2 * mt + 1] += v2 * v2 + v3 * v3;
                }
            }
        }
        __syncthreads();
        float* sred = (float*)sm;
        if (tid < 128) { sred[tid] = 0.f; sred[128 + tid] = 0.f; }
        __syncthreads();
        #pragma unroll
        for (int i = 0; i < 8; i++) {
            int lr = wr * 64 + (i >> 1) * 16 + g + (i & 1) * 8;
            atomicAdd(&sred[lr], sumr[i]);
            atomicAdd(&sred[128 + lr], sqr[i]);
        }
        __syncthreads();
        if (tid < 128) {
            atomicAdd(&d_Sum[rowA + tid], sred[tid]);
            atomicAdd(&d_Sq [rowA + tid], sred[128 + tid]);
        }
    }
}

// ---------------- reduce G2 partials (2-way) -> d_F16 ----------------
__global__ void reduce_f_k()
{
    const size_t per = (size_t)B_ * CI * CI;
    size_t gid = (size_t)blockIdx.x * 256 + threadIdx.x;
    size_t i4 = gid * 4;
    if (i4 >= per) return;
    float4 s0 = *(const float4*)(d_GP + i4);
    float4 s1 = *(const float4*)(d_GP + per + i4);
    *(__half2*)(d_F16 + i4)     = __floats2half2_rn(s0.x + s1.x, s0.y + s1.y);
    *(__half2*)(d_F16 + i4 + 2) = __floats2half2_rn(s0.z + s1.z, s0.w + s1.w);
}

// ---------------- BN finalize / apply ----------------
__global__ void finalize_k(const float* __restrict__ gamma, const float* __restrict__ beta)
{
    int c = threadIdx.x;
    if (c < CIN) {
        const float cnt = (float)((long long)B_ * NPIX);
        float mean = d_Sum[c] / cnt;
        float var  = d_Sq[c] / cnt - mean * mean;
        float s = gamma[c] * rsqrtf(var + EPSV);
        d_Scale[c] = s;
        d_Shift[c] = beta[c] - mean * s;
    }
}

__global__ void apply_k(float* __restrict__ out)
{
    const long long n4 = (long long)B_ * CIN * NPIX / 4;
    const long long stride = (long long)gridDim.x * blockDim.x;
    for (long long i = (long long)blockIdx.x * blockDim.x + threadIdx.x; i < n4; i += stride) {
        int c = (int)((i / (NPIX / 4)) % CIN);
        float s = d_Scale[c], sh = d_Shift[c];
        float4 v = ((float4*)out)[i];
        v.x = v.x * s + sh; v.y = v.y * s + sh;
        v.z = v.z * s + sh; v.w = v.w * s + sh;
        ((float4*)out)[i] = v;
    }
}

// ---------------- launch ----------------
extern "C" void kernel_launch(void* const* d_in, const int* in_sizes, int n_in,
                              void* d_out, int out_size)
{
    const float* x       = (const float*)d_in[0];
    const float* g_w     = (const float*)d_in[1];
    const float* g_b     = (const float*)d_in[2];
    const float* theta_w = (const float*)d_in[3];
    const float* theta_b = (const float*)d_in[4];
    const float* phi_w   = (const float*)d_in[5];
    const float* phi_b   = (const float*)d_in[6];
    const float* W_w     = (const float*)d_in[7];
    const float* W_b     = (const float*)d_in[8];
    const float* gamma   = (const float*)d_in[9];
    const float* beta    = (const float*)d_in[10];
    float* out = (float*)d_out;

    __half *xt, *gt, *tp, *f16, *yt, *wc16, *wr16;
    float *bcat;
    cudaGetSymbolAddress((void**)&xt,   d_XT16);
    cudaGetSymbolAddress((void**)&gt,   d_GT);
    cudaGetSymbolAddress((void**)&tp,   d_TP);
    cudaGetSymbolAddress((void**)&f16,  d_F16);
    cudaGetSymbolAddress((void**)&yt,   d_YT);
    cudaGetSymbolAddress((void**)&wc16, d_Wcat16);
    cudaGetSymbolAddress((void**)&wr16, d_Wr16);
    cudaGetSymbolAddress((void**)&bcat, d_Bcat);

    constexpr int SMEM = 4 * 5120 * 4;               // 81920 B
    cudaFuncSetAttribute(gemm16<3, 1>, cudaFuncAttributeMaxDynamicSharedMemorySize, SMEM);
    cudaFuncSetAttribute(gemm16<2, 2>, cudaFuncAttributeMaxDynamicSharedMemorySize, SMEM);
    cudaFuncSetAttribute(gemm16<0, 1>, cudaFuncAttributeMaxDynamicSharedMemorySize, SMEM);
    cudaFuncSetAttribute(gemm16<1, 1>, cudaFuncAttributeMaxDynamicSharedMemorySize, SMEM);

    const long long sX   = (long long)CIN * NPIX;       // x / out per batch
    const long long sXT  = (long long)NPIX * CIN;
    const long long sGT  = (long long)NPIX * CI;
    const long long sTP  = (long long)CIN * NPIX;
    const long long sF   = (long long)CI * CI;
    const long long sYT  = (long long)NPIX * CI;

    // 0) prep weights + x transpose
    prep_w<<<1536, 256>>>(g_w, g_b, theta_w, theta_b, phi_w, phi_b, W_w);
    xT_k<<<dim3(49, 8, B_), 256>>>(x);

    // 1) G1: xT16 @ Wcat^T + Bcat -> theta|phi into TP[ch][pix], g into GT[pix][256]
    gemm16<3, 1><<<dim3(6, 25, B_), 256, SMEM>>>(
        NPIX, 3 * CI, CIN / 32, 1.f,
        xt, CIN, sXT,
        wc16, CIN, 0,
        nullptr, 0, 0,
        bcat, nullptr, 0);

    // 2) split-K(2) gram: partials[sp][b] = theta @ phi^T / N over K chunk sp
    gemm16<2, 2><<<dim3(2, 2, B_ * 2), 256, SMEM>>>(
        CI, CI, NPIX / 32, 1.f / (float)NPIX,
        tp, NPIX, sTP,
        tp + (long long)CI * NPIX, NPIX, sTP,
        nullptr, CI, sF,
        nullptr, nullptr, 0);

    // 2b) reduce partials -> f16
    reduce_f_k<<<(B_ * CI * CI / 4 + 255) / 256, 256>>>();

    // 3) yT[pix][c] = GT[pix][256k] @ f[c][256k]^T
    gemm16<0, 1><<<dim3(2, 25, B_), 256, SMEM>>>(
        NPIX, CI, CI / 32, 1.f,
        gt, CI, sGT,
        f16, CI, sF,
        yt, CI, sYT,
        nullptr, nullptr, 0);

    // 4) z[ch][pix] = Wr16[512ch][256k] @ yT[pix][256k]^T + W_b[ch] + x  (row stats)
    gemm16<1, 1><<<dim3(25, 4, B_), 256, SMEM>>>(
        CIN, NPIX, CI / 32, 1.f,
        wr16, CI, 0,
        yt, CI, sYT,
        out, NPIX, sX,
        W_b, x, sX);

    // 5) BN finalize + apply
    finalize_k<<<1, 512>>>(gamma, beta);
    apply_k<<<2368, 256>>>(out);
}